// round 11
// baseline (speedup 1.0000x reference)
#include <cuda_runtime.h>
#include <cstdint>

// Problem constants
#define B_   4
#define S_   1024
#define D_   1024
#define H_   16
#define HD_  64
#define QKVN 3072
#define M_   (B_ * S_)

// Scratch (static device globals — allocation-free per harness rules)
__device__ float g_qkv[(size_t)M_ * QKVN];     // [b,s, h*192 + {q,k,v}*64]
__device__ float g_ctx[(size_t)M_ * D_];       // [b,s, h*64+d]
__device__ float2 g_part[(size_t)B_ * H_ * S_ * 8];
__device__ float g_wt[(size_t)QKVN * D_];      // Wqkv^T : [n][k]
__device__ float g_wot[(size_t)D_ * D_];       // Wo^T   : [n][k]

// ---------------------------------------------------------------------------
// helpers
// ---------------------------------------------------------------------------
__device__ __forceinline__ float to_tf32(float x) {
    uint32_t u;
    asm("cvt.rna.tf32.f32 %0, %1;" : "=r"(u) : "f"(x));
    return __uint_as_float(u);
}

__device__ __forceinline__ void mma_tf32(float* d, const uint32_t* a, const uint32_t* b) {
    asm volatile(
        "mma.sync.aligned.m16n8k8.row.col.f32.tf32.tf32.f32 "
        "{%0,%1,%2,%3}, {%4,%5,%6,%7}, {%8,%9}, {%0,%1,%2,%3};\n"
        : "+f"(d[0]), "+f"(d[1]), "+f"(d[2]), "+f"(d[3])
        : "r"(a[0]), "r"(a[1]), "r"(a[2]), "r"(a[3]), "r"(b[0]), "r"(b[1]));
}

// ---------------------------------------------------------------------------
// transpose: Wt[n][k] = W[k][n]   (W is [K][N] row-major)
// ---------------------------------------------------------------------------
__global__ __launch_bounds__(256) void transpose_kernel(
    const float* __restrict__ W, float* __restrict__ Wt, int N, int K)
{
    __shared__ float t[32][33];
    const int n0 = blockIdx.x * 32, k0 = blockIdx.y * 32;
    const int tx = threadIdx.x & 31, ty = threadIdx.x >> 5;  // 32 x 8
#pragma unroll
    for (int i = 0; i < 4; i++)
        t[ty + 8 * i][tx] = W[(size_t)(k0 + ty + 8 * i) * N + n0 + tx];
    __syncthreads();
#pragma unroll
    for (int i = 0; i < 4; i++)
        Wt[(size_t)(n0 + ty + 8 * i) * K + k0 + tx] = t[tx][ty + 8 * i];
}

// ---------------------------------------------------------------------------
// Vectorized-fragment tf32 GEMM: C[M x N] = A[M x K] @ Bt[N x K]^T + bias.
// 128x128 tile, BK=32, 8 warps (4M x 2N), warp tile 32x64.
// Tiles stored k-permuted (p = (k&3)*8 + (k>>2)) so each thread's fragment
// set is contiguous: 24 LDS.128 per BK instead of 96 scalar LDS.
// Frag loads conflict-free at stride 36; staging STS 2-way.
// ---------------------------------------------------------------------------
#define ASTR 36
#define BSTR 36

__device__ __forceinline__ void gemm_v_body(
    const float* __restrict__ A, const float* __restrict__ Bt,
    const float* __restrict__ bias, float* __restrict__ C,
    int N, int K)
{
    __shared__ float As[128 * ASTR];
    __shared__ float Bs[128 * BSTR];

    const int tid  = threadIdx.x;
    const int lane = tid & 31;
    const int wid  = tid >> 5;
    const int wm   = (wid & 3) * 32;
    const int wn   = (wid >> 2) * 64;
    const int bx   = blockIdx.x * 128;
    const int by   = blockIdx.y * 128;
    const int g = lane >> 2;
    const int a = lane & 3;

    float acc[2][8][4];
#pragma unroll
    for (int i = 0; i < 2; i++)
#pragma unroll
        for (int j = 0; j < 8; j++)
#pragma unroll
            for (int v = 0; v < 4; v++) acc[i][j][v] = 0.f;

    const int srow = tid >> 3;     // 0..31 (+32*i)
    const int sc   = tid & 7;      // k/4 within BK

    for (int k0 = 0; k0 < K; k0 += 32) {
        float4 av[4], bv[4];
#pragma unroll
        for (int i = 0; i < 4; i++)
            av[i] = *(const float4*)(A + (size_t)(by + srow + 32 * i) * K + k0 + 4 * sc);
#pragma unroll
        for (int i = 0; i < 4; i++)
            bv[i] = *(const float4*)(Bt + (size_t)(bx + srow + 32 * i) * K + k0 + 4 * sc);

        __syncthreads();
#pragma unroll
        for (int i = 0; i < 4; i++) {
            float* r = As + (srow + 32 * i) * ASTR + sc;
            r[0]  = to_tf32(av[i].x);
            r[8]  = to_tf32(av[i].y);
            r[16] = to_tf32(av[i].z);
            r[24] = to_tf32(av[i].w);
        }
#pragma unroll
        for (int i = 0; i < 4; i++) {
            float* r = Bs + (srow + 32 * i) * BSTR + sc;
            r[0]  = to_tf32(bv[i].x);
            r[8]  = to_tf32(bv[i].y);
            r[16] = to_tf32(bv[i].z);
            r[24] = to_tf32(bv[i].w);
        }
        __syncthreads();

#pragma unroll
        for (int half = 0; half < 2; half++) {
            float4 alo[4];
#pragma unroll
            for (int ii = 0; ii < 4; ii++)
                alo[ii] = *(const float4*)(As + (wm + 8 * ii + g) * ASTR + a * 8 + half * 4);

#pragma unroll
            for (int jh = 0; jh < 2; jh++) {
                float4 blo[4];
#pragma unroll
                for (int jj = 0; jj < 4; jj++)
                    blo[jj] = *(const float4*)(Bs + (wn + (jh * 4 + jj) * 8 + g) * BSTR + a * 8 + half * 4);

                // kk = 32*?: s2=0 -> components .x/.y, s2=1 -> .z/.w
                {
                    uint32_t af0[4] = {__float_as_uint(alo[0].x), __float_as_uint(alo[1].x),
                                       __float_as_uint(alo[0].y), __float_as_uint(alo[1].y)};
                    uint32_t af1[4] = {__float_as_uint(alo[2].x), __float_as_uint(alo[3].x),
                                       __float_as_uint(alo[2].y), __float_as_uint(alo[3].y)};
#pragma unroll
                    for (int jj = 0; jj < 4; jj++) {
                        uint32_t bf[2] = {__float_as_uint(blo[jj].x), __float_as_uint(blo[jj].y)};
                        mma_tf32(acc[0][jh * 4 + jj], af0, bf);
                        mma_tf32(acc[1][jh * 4 + jj], af1, bf);
                    }
                }
                {
                    uint32_t af0[4] = {__float_as_uint(alo[0].z), __float_as_uint(alo[1].z),
                                       __float_as_uint(alo[0].w), __float_as_uint(alo[1].w)};
                    uint32_t af1[4] = {__float_as_uint(alo[2].z), __float_as_uint(alo[3].z),
                                       __float_as_uint(alo[2].w), __float_as_uint(alo[3].w)};
#pragma unroll
                    for (int jj = 0; jj < 4; jj++) {
                        uint32_t bf[2] = {__float_as_uint(blo[jj].z), __float_as_uint(blo[jj].w)};
                        mma_tf32(acc[0][jh * 4 + jj], af0, bf);
                        mma_tf32(acc[1][jh * 4 + jj], af1, bf);
                    }
                }
            }
        }
    }

#pragma unroll
    for (int i = 0; i < 2; i++) {
        int row = by + wm + i * 16 + g;
#pragma unroll
        for (int j = 0; j < 8; j++) {
            int col = bx + wn + j * 8 + a * 2;
            float b0 = bias[col], b1 = bias[col + 1];
            *(float2*)(C + (size_t)row * N + col) =
                make_float2(acc[i][j][0] + b0, acc[i][j][1] + b1);
            *(float2*)(C + (size_t)(row + 8) * N + col) =
                make_float2(acc[i][j][2] + b0, acc[i][j][3] + b1);
        }
    }
}

__global__ __launch_bounds__(256) void qkv_gemm_kernel(
    const float* __restrict__ x, const float* __restrict__ bias)
{
    gemm_v_body(x, g_wt, bias, g_qkv, QKVN, D_);
}

__global__ __launch_bounds__(256) void out_gemm_kernel(
    const float* __restrict__ bias, float* __restrict__ out)
{
    gemm_v_body(g_ctx, g_wot, bias, out, D_, D_);
}

// ---------------------------------------------------------------------------
// scores kernel (FROZEN from R9)
// ---------------------------------------------------------------------------
#define SC_STR 68
#define SCORES_SMEM ((128 * SC_STR * 2) * 4)

__global__ __launch_bounds__(256) void scores_kernel(
    const float* __restrict__ mask, float* __restrict__ att)
{
    extern __shared__ float sms[];
    float* Qs = sms;
    float* Ks = sms + 128 * SC_STR;
    __shared__ float sm_part[128][2][2];

    const int bh = blockIdx.z;
    const int b  = bh >> 4, h = bh & 15;
    const int qt = blockIdx.y * 128;
    const int kt = blockIdx.x * 128;
    const int tid = threadIdx.x;
    const int lane = tid & 31, w = tid >> 5;
    const int g = lane >> 2, a = lane & 3;
    const int wm = (w & 3) * 32, wn = (w >> 2) * 64;

    const float* qkv_b = g_qkv + (size_t)(b * S_) * QKVN + h * 192;

    {
        int row = tid >> 4;
        int c4  = (tid & 15) * 4;
#pragma unroll
        for (int i = 0; i < 8; i++) {
            float4 t = *(const float4*)(qkv_b + (size_t)(qt + row + 16 * i) * QKVN + c4);
            t.x = to_tf32(t.x * 0.125f); t.y = to_tf32(t.y * 0.125f);
            t.z = to_tf32(t.z * 0.125f); t.w = to_tf32(t.w * 0.125f);
            *(float4*)(Qs + (row + 16 * i) * SC_STR + c4) = t;
        }
#pragma unroll
        for (int i = 0; i < 8; i++) {
            float4 t = *(const float4*)(qkv_b + (size_t)(kt + row + 16 * i) * QKVN + 64 + c4);
            t.x = to_tf32(t.x); t.y = to_tf32(t.y); t.z = to_tf32(t.z); t.w = to_tf32(t.w);
            *(float4*)(Ks + (row + 16 * i) * SC_STR + c4) = t;
        }
    }
    __syncthreads();

    float acc[2][8][4];
#pragma unroll
    for (int i = 0; i < 2; i++)
#pragma unroll
        for (int j = 0; j < 8; j++)
#pragma unroll
            for (int v = 0; v < 4; v++) acc[i][j][v] = 0.f;

#pragma unroll
    for (int ks = 0; ks < 8; ks++) {
        int k0 = ks * 8;
        uint32_t af[2][4], bf[8][2];
#pragma unroll
        for (int i = 0; i < 2; i++) {
            int r = wm + i * 16 + g;
            af[i][0] = __float_as_uint(Qs[(r)     * SC_STR + k0 + a]);
            af[i][1] = __float_as_uint(Qs[(r + 8) * SC_STR + k0 + a]);
            af[i][2] = __float_as_uint(Qs[(r)     * SC_STR + k0 + 4 + a]);
            af[i][3] = __float_as_uint(Qs[(r + 8) * SC_STR + k0 + 4 + a]);
        }
#pragma unroll
        for (int j = 0; j < 8; j++) {
            int n = wn + j * 8 + g;
            bf[j][0] = __float_as_uint(Ks[n * SC_STR + k0 + a]);
            bf[j][1] = __float_as_uint(Ks[n * SC_STR + k0 + 4 + a]);
        }
#pragma unroll
        for (int i = 0; i < 2; i++)
#pragma unroll
            for (int j = 0; j < 8; j++)
                mma_tf32(acc[i][j], af[i], bf[j]);
    }

    float* abase = att + ((size_t)(b * H_ + h) * S_ + qt) * S_ + kt;
    const float* mbase = mask + ((size_t)(b * S_) + qt) * S_ + kt;
#pragma unroll
    for (int i = 0; i < 2; i++) {
        int r0 = wm + i * 16 + g;
        float mx0 = -1e30f, mx1 = -1e30f;
#pragma unroll
        for (int j = 0; j < 8; j++) {
            int col = wn + j * 8 + a * 2;
            float2 m0 = *(const float2*)(mbase + (size_t)r0 * S_ + col);
            float2 m1 = *(const float2*)(mbase + (size_t)(r0 + 8) * S_ + col);
            acc[i][j][0] += m0.x; acc[i][j][1] += m0.y;
            acc[i][j][2] += m1.x; acc[i][j][3] += m1.y;
            *(float2*)(abase + (size_t)r0 * S_ + col) =
                make_float2(acc[i][j][0], acc[i][j][1]);
            *(float2*)(abase + (size_t)(r0 + 8) * S_ + col) =
                make_float2(acc[i][j][2], acc[i][j][3]);
            mx0 = fmaxf(mx0, fmaxf(acc[i][j][0], acc[i][j][1]));
            mx1 = fmaxf(mx1, fmaxf(acc[i][j][2], acc[i][j][3]));
        }
        mx0 = fmaxf(mx0, __shfl_xor_sync(~0u, mx0, 1));
        mx0 = fmaxf(mx0, __shfl_xor_sync(~0u, mx0, 2));
        mx1 = fmaxf(mx1, __shfl_xor_sync(~0u, mx1, 1));
        mx1 = fmaxf(mx1, __shfl_xor_sync(~0u, mx1, 2));
        float s0 = 0.f, s1 = 0.f;
#pragma unroll
        for (int j = 0; j < 8; j++) {
            s0 += __expf(acc[i][j][0] - mx0) + __expf(acc[i][j][1] - mx0);
            s1 += __expf(acc[i][j][2] - mx1) + __expf(acc[i][j][3] - mx1);
        }
        s0 += __shfl_xor_sync(~0u, s0, 1); s0 += __shfl_xor_sync(~0u, s0, 2);
        s1 += __shfl_xor_sync(~0u, s1, 1); s1 += __shfl_xor_sync(~0u, s1, 2);
        if (a == 0) {
            int half = wn >> 6;
            sm_part[r0][half][0]     = mx0; sm_part[r0][half][1]     = s0;
            sm_part[r0 + 8][half][0] = mx1; sm_part[r0 + 8][half][1] = s1;
        }
    }
    __syncthreads();
    if (tid < 128) {
        float m0 = sm_part[tid][0][0], s0 = sm_part[tid][0][1];
        float m1 = sm_part[tid][1][0], s1 = sm_part[tid][1][1];
        float M = fmaxf(m0, m1);
        float S = s0 * __expf(m0 - M) + s1 * __expf(m1 - M);
        g_part[((size_t)bh * S_ + qt + tid) * 8 + blockIdx.x] = make_float2(M, S);
    }
}

// ---------------------------------------------------------------------------
// ctx kernel (FROZEN from R9)
// ---------------------------------------------------------------------------
#define CT_ASTR 68
#define CT_VSTR 72
#define CT_AT   (128 * CT_ASTR)
#define CT_VT   (64 * CT_VSTR)
#define CTX_SMEM (2 * (CT_AT + CT_VT) * 4)

__global__ __launch_bounds__(256) void ctx_kernel(float* __restrict__ att)
{
    extern __shared__ float smcx[];
    float* As = smcx;
    float* Vs = smcx + 2 * CT_AT;
    __shared__ float sm_M[128], sm_inv[128];

    const int bh = blockIdx.y;
    const int b  = bh >> 4, h = bh & 15;
    const int mt = blockIdx.x * 128;
    const int tid = threadIdx.x;
    const int lane = tid & 31, w = tid >> 5;
    const int g = lane >> 2, a = lane & 3;
    const int wm = (w & 3) * 32, wn = (w >> 2) * 32;

    float* abase = att + ((size_t)bh * S_ + mt) * S_;
    const float* vbase = g_qkv + (size_t)(b * S_) * QKVN + h * 192 + 128;

    const int lrow = tid >> 4;
    const int lc4  = (tid & 15) * 4;

    if (tid < 128) {
        const float2* pp = g_part + ((size_t)bh * S_ + mt + tid) * 8;
        float2 t[8];
#pragma unroll
        for (int k = 0; k < 8; k++) t[k] = pp[k];
        float M = t[0].x;
#pragma unroll
        for (int k = 1; k < 8; k++) M = fmaxf(M, t[k].x);
        float S = 0.f;
#pragma unroll
        for (int k = 0; k < 8; k++) S += t[k].y * __expf(t[k].x - M);
        sm_M[tid] = M;
        sm_inv[tid] = 1.f / S;
    }
    __syncthreads();

    float rowM[8], rowInv[8];
#pragma unroll
    for (int i = 0; i < 8; i++) {
        rowM[i]   = sm_M[lrow + 16 * i];
        rowInv[i] = sm_inv[lrow + 16 * i];
    }

    float4 avr[8], bvr[4];

#define A_LDG(c)                                                               \
    {                                                                          \
        _Pragma("unroll")                                                      \
        for (int i = 0; i < 8; i++)                                            \
            avr[i] = *(const float4*)(abase + (size_t)(lrow + 16 * i) * S_ +   \
                                      (c) * 64 + lc4);                         \
    }
#define A_STS(buf, c)                                                          \
    {                                                                          \
        float* dst = As + (buf) * CT_AT;                                       \
        _Pragma("unroll")                                                      \
        for (int i = 0; i < 8; i++) {                                          \
            float4 t = avr[i];                                                 \
            t.x = __expf(t.x - rowM[i]) * rowInv[i];                           \
            t.y = __expf(t.y - rowM[i]) * rowInv[i];                           \
            t.z = __expf(t.z - rowM[i]) * rowInv[i];                           \
            t.w = __expf(t.w - rowM[i]) * rowInv[i];                           \
            *(float4*)(abase + (size_t)(lrow + 16 * i) * S_ + (c) * 64 + lc4) = t; \
            t.x = to_tf32(t.x); t.y = to_tf32(t.y);                            \
            t.z = to_tf32(t.z); t.w = to_tf32(t.w);                            \
            *(float4*)(dst + (lrow + 16 * i) * CT_ASTR + lc4) = t;             \
        }                                                                      \
    }
#define V_LDG(c)                                                               \
    {                                                                          \
        _Pragma("unroll")                                                      \
        for (int i = 0; i < 4; i++)                                            \
            bvr[i] = *(const float4*)(vbase +                                  \
                (size_t)((c) * 64 + lrow + 16 * i) * QKVN + lc4);              \
    }
#define V_STS(buf)                                                             \
    {                                                                          \
        float* dst = Vs + (buf) * CT_VT;                                       \
        _Pragma("unroll")                                                      \
        for (int i = 0; i < 4; i++) {                                          \
            float4 t = bvr[i];                                                 \
            t.x = to_tf32(t.x); t.y = to_tf32(t.y);                            \
            t.z = to_tf32(t.z); t.w = to_tf32(t.w);                            \
            *(float4*)(dst + (lrow + 16 * i) * CT_VSTR + lc4) = t;             \
        }                                                                      \
    }

    float acc[2][4][4];
#pragma unroll
    for (int i = 0; i < 2; i++)
#pragma unroll
        for (int j = 0; j < 4; j++)
#pragma unroll
            for (int v = 0; v < 4; v++) acc[i][j][v] = 0.f;

    const int nk = S_ / 64;
    A_LDG(0); A_STS(0, 0);
    V_LDG(0); V_STS(0);
    A_LDG(1); V_LDG(1);
    __syncthreads();

    for (int c = 0; c < nk; c++) {
        const float* Ab_ = As + (c & 1) * CT_AT;
        const float* Vb_ = Vs + (c & 1) * CT_VT;
        if (c + 1 < nk) { A_STS((c + 1) & 1, c + 1); V_STS((c + 1) & 1); }
        if (c + 2 < nk) { A_LDG(c + 2); V_LDG(c + 2); }

#pragma unroll
        for (int kk = 0; kk < 64; kk += 8) {
            uint32_t af[2][4], bf[4][2];
#pragma unroll
            for (int i = 0; i < 2; i++) {
                int r = wm + i * 16 + g;
                af[i][0] = __float_as_uint(Ab_[(r)     * CT_ASTR + kk + a]);
                af[i][1] = __float_as_uint(Ab_[(r + 8) * CT_ASTR + kk + a]);
                af[i][2] = __float_as_uint(Ab_[(r)     * CT_ASTR + kk + 4 + a]);
                af[i][3] = __float_as_uint(Ab_[(r + 8) * CT_ASTR + kk + 4 + a]);
            }
#pragma unroll
            for (int j = 0; j < 4; j++) {
                int n = wn + j * 8 + g;
                bf[j][0] = __float_as_uint(Vb_[(kk + a)     * CT_VSTR + n]);
                bf[j][1] = __float_as_uint(Vb_[(kk + 4 + a) * CT_VSTR + n]);
            }
#pragma unroll
            for (int i = 0; i < 2; i++)
#pragma unroll
                for (int j = 0; j < 4; j++)
                    mma_tf32(acc[i][j], af[i], bf[j]);
        }
        __syncthreads();
    }
#undef A_LDG
#undef A_STS
#undef V_LDG
#undef V_STS

#pragma unroll
    for (int i = 0; i < 2; i++) {
        int row = mt + wm + i * 16 + g;
#pragma unroll
        for (int j = 0; j < 4; j++) {
            int col = wn + j * 8 + a * 2;
            *(float2*)(g_ctx + (size_t)(b * S_ + row) * D_ + h * HD_ + col) =
                make_float2(acc[i][j][0], acc[i][j][1]);
            *(float2*)(g_ctx + (size_t)(b * S_ + row + 8) * D_ + h * HD_ + col) =
                make_float2(acc[i][j][2], acc[i][j][3]);
        }
    }
}

// ---------------------------------------------------------------------------
extern "C" void kernel_launch(void* const* d_in, const int* in_sizes, int n_in,
                              void* d_out, int out_size)
{
    const float* x    = (const float*)d_in[0];
    const float* mask = (const float*)d_in[1];
    const float* Wqkv = (const float*)d_in[2];
    const float* bqkv = (const float*)d_in[3];
    const float* Wo   = (const float*)d_in[4];
    const float* bo   = (const float*)d_in[5];

    float* out = (float*)d_out;                       // [B,S,D]
    float* att = out + (size_t)B_ * S_ * D_;          // [B,H,S,S]

    cudaFuncSetAttribute(scores_kernel,
                         cudaFuncAttributeMaxDynamicSharedMemorySize, SCORES_SMEM);
    cudaFuncSetAttribute(ctx_kernel,
                         cudaFuncAttributeMaxDynamicSharedMemorySize, CTX_SMEM);

    // get symbol pointers via kernel params (globals referenced directly)
    // 0) transpose weights to [n][k]
    {
        float* wt_p;  cudaGetSymbolAddress((void**)&wt_p, g_wt);
        float* wot_p; cudaGetSymbolAddress((void**)&wot_p, g_wot);
        dim3 g1(QKVN / 32, D_ / 32);
        transpose_kernel<<<g1, 256>>>(Wqkv, wt_p, QKVN, D_);
        dim3 g2(D_ / 32, D_ / 32);
        transpose_kernel<<<g2, 256>>>(Wo, wot_p, D_, D_);
    }
    // 1) fused QKV projection (vectorized-fragment tf32 GEMM)
    {
        dim3 grid(QKVN / 128, M_ / 128);
        qkv_gemm_kernel<<<grid, 256>>>(x, bqkv);
    }
    // 2a) raw scores + mask + softmax partials
    {
        dim3 grid(S_ / 128, S_ / 128, B_ * H_);
        scores_kernel<<<grid, 256, SCORES_SMEM>>>(mask, att);
    }
    // 2b) ctx = softmax(att) @ V, normalized att written in-flight
    {
        dim3 grid(S_ / 128, B_ * H_);
        ctx_kernel<<<grid, 256, CTX_SMEM>>>(att);
    }
    // 3) output projection
    {
        dim3 grid(D_ / 128, M_ / 128);
        out_gemm_kernel<<<grid, 256>>>(bo, out);
    }
}

// round 12
// speedup vs baseline: 1.1337x; 1.1337x over previous
#include <cuda_runtime.h>
#include <cstdint>

// Problem constants
#define B_   4
#define S_   1024
#define D_   1024
#define H_   16
#define HD_  64
#define QKVN 3072
#define M_   (B_ * S_)

// Scratch (static device globals — allocation-free per harness rules)
__device__ float g_qkv[(size_t)M_ * QKVN];     // [b,s, h*192 + {q,k,v}*64]
__device__ float g_ctx[(size_t)M_ * D_];       // [b,s, h*64+d]
__device__ float2 g_part[(size_t)B_ * H_ * S_ * 16];  // per (bh,q,half64): (max, expsum)

// ---------------------------------------------------------------------------
// helpers
// ---------------------------------------------------------------------------
__device__ __forceinline__ float to_tf32(float x) {
    uint32_t u;
    asm("cvt.rna.tf32.f32 %0, %1;" : "=r"(u) : "f"(x));
    return __uint_as_float(u);
}

__device__ __forceinline__ void mma_tf32(float* d, const uint32_t* a, const uint32_t* b) {
    asm volatile(
        "mma.sync.aligned.m16n8k8.row.col.f32.tf32.tf32.f32 "
        "{%0,%1,%2,%3}, {%4,%5,%6,%7}, {%8,%9}, {%0,%1,%2,%3};\n"
        : "+f"(d[0]), "+f"(d[1]), "+f"(d[2]), "+f"(d[3])
        : "r"(a[0]), "r"(a[1]), "r"(a[2]), "r"(a[3]), "r"(b[0]), "r"(b[1]));
}

// ---------------------------------------------------------------------------
// tf32 GEMM (proven form, FROZEN): 128x128 tile, BK=32, 8 warps (4M x 2N),
// warp tile 32x64, static smem, single buffer.
// ---------------------------------------------------------------------------
#define BK   32
#define ASTR 36
#define BSTR 136

__device__ __forceinline__ void gemm_tf32_body(
    const float* __restrict__ A, const float* __restrict__ Bm,
    const float* __restrict__ bias, float* __restrict__ C,
    int N, int K)
{
    __shared__ float As[128 * ASTR];
    __shared__ float Bs[BK * BSTR];

    const int tid  = threadIdx.x;
    const int lane = tid & 31;
    const int wid  = tid >> 5;
    const int wm   = (wid & 3) * 32;
    const int wn   = (wid >> 2) * 64;
    const int bx   = blockIdx.x * 128;
    const int by   = blockIdx.y * 128;

    const int g = lane >> 2;
    const int a = lane & 3;

    float acc[2][8][4];
#pragma unroll
    for (int i = 0; i < 2; i++)
#pragma unroll
        for (int j = 0; j < 8; j++)
#pragma unroll
            for (int v = 0; v < 4; v++) acc[i][j][v] = 0.f;

    const int arow0 = tid >> 3;
    const int acol  = (tid & 7) * 4;
    const int brow0 = tid >> 5;
    const int bcol  = (tid & 31) * 4;

    for (int k0 = 0; k0 < K; k0 += BK) {
        float4 av[4], bv[4];
#pragma unroll
        for (int i = 0; i < 4; i++)
            av[i] = *(const float4*)(A + (size_t)(by + arow0 + 32 * i) * K + k0 + acol);
#pragma unroll
        for (int i = 0; i < 4; i++)
            bv[i] = *(const float4*)(Bm + (size_t)(k0 + brow0 + 8 * i) * N + bx + bcol);

        __syncthreads();
#pragma unroll
        for (int i = 0; i < 4; i++) {
            float4 t = av[i];
            t.x = to_tf32(t.x); t.y = to_tf32(t.y); t.z = to_tf32(t.z); t.w = to_tf32(t.w);
            *(float4*)(As + (arow0 + 32 * i) * ASTR + acol) = t;
        }
#pragma unroll
        for (int i = 0; i < 4; i++) {
            float4 t = bv[i];
            t.x = to_tf32(t.x); t.y = to_tf32(t.y); t.z = to_tf32(t.z); t.w = to_tf32(t.w);
            *(float4*)(Bs + (brow0 + 8 * i) * BSTR + bcol) = t;
        }
        __syncthreads();

#pragma unroll
        for (int kk = 0; kk < BK; kk += 8) {
            uint32_t af[2][4], bf[8][2];
#pragma unroll
            for (int i = 0; i < 2; i++) {
                int r = wm + i * 16 + g;
                af[i][0] = __float_as_uint(As[(r)     * ASTR + kk + a]);
                af[i][1] = __float_as_uint(As[(r + 8) * ASTR + kk + a]);
                af[i][2] = __float_as_uint(As[(r)     * ASTR + kk + 4 + a]);
                af[i][3] = __float_as_uint(As[(r + 8) * ASTR + kk + 4 + a]);
            }
#pragma unroll
            for (int j = 0; j < 8; j++) {
                int n = wn + j * 8 + g;
                bf[j][0] = __float_as_uint(Bs[(kk + a)     * BSTR + n]);
                bf[j][1] = __float_as_uint(Bs[(kk + 4 + a) * BSTR + n]);
            }
#pragma unroll
            for (int i = 0; i < 2; i++)
#pragma unroll
                for (int j = 0; j < 8; j++)
                    mma_tf32(acc[i][j], af[i], bf[j]);
        }
    }

#pragma unroll
    for (int i = 0; i < 2; i++) {
        int row = by + wm + i * 16 + g;
#pragma unroll
        for (int j = 0; j < 8; j++) {
            int col = bx + wn + j * 8 + a * 2;
            float b0 = bias[col], b1 = bias[col + 1];
            *(float2*)(C + (size_t)row * N + col) =
                make_float2(acc[i][j][0] + b0, acc[i][j][1] + b1);
            *(float2*)(C + (size_t)(row + 8) * N + col) =
                make_float2(acc[i][j][2] + b0, acc[i][j][3] + b1);
        }
    }
}

__global__ __launch_bounds__(256) void qkv_gemm_kernel(
    const float* __restrict__ x, const float* __restrict__ W,
    const float* __restrict__ bias)
{
    gemm_tf32_body(x, W, bias, g_qkv, QKVN, D_);
}

__global__ __launch_bounds__(256) void out_gemm_kernel(
    const float* __restrict__ W, const float* __restrict__ bias,
    float* __restrict__ out)
{
    gemm_tf32_body(g_ctx, W, bias, out, D_, D_);
}

// ---------------------------------------------------------------------------
// scores kernel: computes s = (Q*0.125)K^T + mask, then writes
// e = exp(s - m_half) to att (NOT raw scores) and per-(row, half64)
// partials (m_half, sum e) straight to g_part (16 per row).
// per block: 128q x 128k of one (b,h). 8 warps (4M x 2N), warp tile 32x64.
// ---------------------------------------------------------------------------
#define SC_STR 68
#define SCORES_SMEM ((128 * SC_STR * 2) * 4)

__global__ __launch_bounds__(256) void scores_kernel(
    const float* __restrict__ mask, float* __restrict__ att)
{
    extern __shared__ float sms[];
    float* Qs = sms;
    float* Ks = sms + 128 * SC_STR;

    const int bh = blockIdx.z;
    const int b  = bh >> 4, h = bh & 15;
    const int qt = blockIdx.y * 128;
    const int kt = blockIdx.x * 128;
    const int tid = threadIdx.x;
    const int lane = tid & 31, w = tid >> 5;
    const int g = lane >> 2, a = lane & 3;
    const int wm = (w & 3) * 32, wn = (w >> 2) * 64;

    const float* qkv_b = g_qkv + (size_t)(b * S_) * QKVN + h * 192;

    {
        int row = tid >> 4;
        int c4  = (tid & 15) * 4;
#pragma unroll
        for (int i = 0; i < 8; i++) {
            float4 t = *(const float4*)(qkv_b + (size_t)(qt + row + 16 * i) * QKVN + c4);
            t.x = to_tf32(t.x * 0.125f); t.y = to_tf32(t.y * 0.125f);
            t.z = to_tf32(t.z * 0.125f); t.w = to_tf32(t.w * 0.125f);
            *(float4*)(Qs + (row + 16 * i) * SC_STR + c4) = t;
        }
#pragma unroll
        for (int i = 0; i < 8; i++) {
            float4 t = *(const float4*)(qkv_b + (size_t)(kt + row + 16 * i) * QKVN + 64 + c4);
            t.x = to_tf32(t.x); t.y = to_tf32(t.y); t.z = to_tf32(t.z); t.w = to_tf32(t.w);
            *(float4*)(Ks + (row + 16 * i) * SC_STR + c4) = t;
        }
    }
    __syncthreads();

    float acc[2][8][4];
#pragma unroll
    for (int i = 0; i < 2; i++)
#pragma unroll
        for (int j = 0; j < 8; j++)
#pragma unroll
            for (int v = 0; v < 4; v++) acc[i][j][v] = 0.f;

#pragma unroll
    for (int ks = 0; ks < 8; ks++) {
        int k0 = ks * 8;
        uint32_t af[2][4], bf[8][2];
#pragma unroll
        for (int i = 0; i < 2; i++) {
            int r = wm + i * 16 + g;
            af[i][0] = __float_as_uint(Qs[(r)     * SC_STR + k0 + a]);
            af[i][1] = __float_as_uint(Qs[(r + 8) * SC_STR + k0 + a]);
            af[i][2] = __float_as_uint(Qs[(r)     * SC_STR + k0 + 4 + a]);
            af[i][3] = __float_as_uint(Qs[(r + 8) * SC_STR + k0 + 4 + a]);
        }
#pragma unroll
        for (int j = 0; j < 8; j++) {
            int n = wn + j * 8 + g;
            bf[j][0] = __float_as_uint(Ks[n * SC_STR + k0 + a]);
            bf[j][1] = __float_as_uint(Ks[n * SC_STR + k0 + 4 + a]);
        }
#pragma unroll
        for (int i = 0; i < 2; i++)
#pragma unroll
            for (int j = 0; j < 8; j++)
                mma_tf32(acc[i][j], af[i], bf[j]);
    }

    // epilogue: + mask, half-max, e = exp(s - m_half) -> att, partials -> g_part
    float* abase = att + ((size_t)(b * H_ + h) * S_ + qt) * S_ + kt;
    const float* mbase = mask + ((size_t)(b * S_) + qt) * S_ + kt;
    const int half = wn >> 6;
#pragma unroll
    for (int i = 0; i < 2; i++) {
        int r0 = wm + i * 16 + g;
        float mx0 = -1e30f, mx1 = -1e30f;
#pragma unroll
        for (int j = 0; j < 8; j++) {
            int col = wn + j * 8 + a * 2;
            float2 m0 = *(const float2*)(mbase + (size_t)r0 * S_ + col);
            float2 m1 = *(const float2*)(mbase + (size_t)(r0 + 8) * S_ + col);
            acc[i][j][0] += m0.x; acc[i][j][1] += m0.y;
            acc[i][j][2] += m1.x; acc[i][j][3] += m1.y;
            mx0 = fmaxf(mx0, fmaxf(acc[i][j][0], acc[i][j][1]));
            mx1 = fmaxf(mx1, fmaxf(acc[i][j][2], acc[i][j][3]));
        }
        mx0 = fmaxf(mx0, __shfl_xor_sync(~0u, mx0, 1));
        mx0 = fmaxf(mx0, __shfl_xor_sync(~0u, mx0, 2));
        mx1 = fmaxf(mx1, __shfl_xor_sync(~0u, mx1, 1));
        mx1 = fmaxf(mx1, __shfl_xor_sync(~0u, mx1, 2));
        float s0 = 0.f, s1 = 0.f;
#pragma unroll
        for (int j = 0; j < 8; j++) {
            int col = wn + j * 8 + a * 2;
            float e00 = __expf(acc[i][j][0] - mx0);
            float e01 = __expf(acc[i][j][1] - mx0);
            float e10 = __expf(acc[i][j][2] - mx1);
            float e11 = __expf(acc[i][j][3] - mx1);
            s0 += e00 + e01;
            s1 += e10 + e11;
            *(float2*)(abase + (size_t)r0 * S_ + col)       = make_float2(e00, e01);
            *(float2*)(abase + (size_t)(r0 + 8) * S_ + col) = make_float2(e10, e11);
        }
        s0 += __shfl_xor_sync(~0u, s0, 1); s0 += __shfl_xor_sync(~0u, s0, 2);
        s1 += __shfl_xor_sync(~0u, s1, 1); s1 += __shfl_xor_sync(~0u, s1, 2);
        if (a == 0) {
            g_part[((size_t)bh * S_ + qt + r0)     * 16 + blockIdx.x * 2 + half] =
                make_float2(mx0, s0);
            g_part[((size_t)bh * S_ + qt + r0 + 8) * 16 + blockIdx.x * 2 + half] =
                make_float2(mx1, s1);
        }
    }
}

// ---------------------------------------------------------------------------
// ctx kernel: combines 16 half-partials -> exact row (M, 1/S); rescales the
// pre-exponentiated e-values by exp(m_c - M)/S (one mul per element, one exp
// per row-chunk), writes normalized att, computes g_ctx = P @ V.
// per block: 128 rows x 64 dims of one (b,h); BK=64 chunks, double-buffered.
// 8 warps (4M x 2N), warp tile 32x32.
// ---------------------------------------------------------------------------
#define CT_ASTR 68
#define CT_VSTR 72
#define CT_AT   (128 * CT_ASTR)
#define CT_VT   (64 * CT_VSTR)
#define CTX_SMEM (2 * (CT_AT + CT_VT) * 4)

__global__ __launch_bounds__(256) void ctx_kernel(float* __restrict__ att)
{
    extern __shared__ float smcx[];
    float* As = smcx;
    float* Vs = smcx + 2 * CT_AT;
    __shared__ float sm_M[128], sm_inv[128];

    const int bh = blockIdx.y;
    const int b  = bh >> 4, h = bh & 15;
    const int mt = blockIdx.x * 128;
    const int tid = threadIdx.x;
    const int lane = tid & 31, w = tid >> 5;
    const int g = lane >> 2, a = lane & 3;
    const int wm = (w & 3) * 32, wn = (w >> 2) * 32;

    float* abase = att + ((size_t)bh * S_ + mt) * S_;
    const float* vbase = g_qkv + (size_t)(b * S_) * QKVN + h * 192 + 128;
    const float* gpf = (const float*)g_part;   // scalar view: [idx*2]=max, [idx*2+1]=sum

    const int lrow = tid >> 4;
    const int lc4  = (tid & 15) * 4;

    // combine the 16 per-half partials into exact row (M, 1/S)
    if (tid < 128) {
        const float2* pp = g_part + ((size_t)bh * S_ + mt + tid) * 16;
        float2 t[16];
#pragma unroll
        for (int k = 0; k < 16; k++) t[k] = pp[k];
        float M = t[0].x;
#pragma unroll
        for (int k = 1; k < 16; k++) M = fmaxf(M, t[k].x);
        float S = 0.f;
#pragma unroll
        for (int k = 0; k < 16; k++) S += t[k].y * __expf(t[k].x - M);
        sm_M[tid] = M;
        sm_inv[tid] = 1.f / S;
    }
    __syncthreads();

    float rowM[8], rowInv[8];
#pragma unroll
    for (int i = 0; i < 8; i++) {
        rowM[i]   = sm_M[lrow + 16 * i];
        rowInv[i] = sm_inv[lrow + 16 * i];
    }

    float4 avr[8], bvr[4];

#define A_LDG(c)                                                               \
    {                                                                          \
        _Pragma("unroll")                                                      \
        for (int i = 0; i < 8; i++)                                            \
            avr[i] = *(const float4*)(abase + (size_t)(lrow + 16 * i) * S_ +   \
                                      (c) * 64 + lc4);                         \
    }
    // rescale e-values by per-(row,chunk) factor + write normalized att + stage
#define A_STS(buf, c)                                                          \
    {                                                                          \
        float* dst = As + (buf) * CT_AT;                                       \
        _Pragma("unroll")                                                      \
        for (int i = 0; i < 8; i++) {                                          \
            float mc = gpf[(((size_t)bh * S_ + mt + lrow + 16 * i) * 16 + (c)) * 2]; \
            float sc_i = __expf(mc - rowM[i]) * rowInv[i];                     \
            float4 t = avr[i];                                                 \
            t.x *= sc_i; t.y *= sc_i; t.z *= sc_i; t.w *= sc_i;                \
            *(float4*)(abase + (size_t)(lrow + 16 * i) * S_ + (c) * 64 + lc4) = t; \
            t.x = to_tf32(t.x); t.y = to_tf32(t.y);                            \
            t.z = to_tf32(t.z); t.w = to_tf32(t.w);                            \
            *(float4*)(dst + (lrow + 16 * i) * CT_ASTR + lc4) = t;             \
        }                                                                      \
    }
#define V_LDG(c)                                                               \
    {                                                                          \
        _Pragma("unroll")                                                      \
        for (int i = 0; i < 4; i++)                                            \
            bvr[i] = *(const float4*)(vbase +                                  \
                (size_t)((c) * 64 + lrow + 16 * i) * QKVN + lc4);              \
    }
#define V_STS(buf)                                                             \
    {                                                                          \
        float* dst = Vs + (buf) * CT_VT;                                       \
        _Pragma("unroll")                                                      \
        for (int i = 0; i < 4; i++) {                                          \
            float4 t = bvr[i];                                                 \
            t.x = to_tf32(t.x); t.y = to_tf32(t.y);                            \
            t.z = to_tf32(t.z); t.w = to_tf32(t.w);                            \
            *(float4*)(dst + (lrow + 16 * i) * CT_VSTR + lc4) = t;             \
        }                                                                      \
    }

    float acc[2][4][4];
#pragma unroll
    for (int i = 0; i < 2; i++)
#pragma unroll
        for (int j = 0; j < 4; j++)
#pragma unroll
            for (int v = 0; v < 4; v++) acc[i][j][v] = 0.f;

    const int nk = S_ / 64;
    A_LDG(0); A_STS(0, 0);
    V_LDG(0); V_STS(0);
    A_LDG(1); V_LDG(1);
    __syncthreads();

    for (int c = 0; c < nk; c++) {
        const float* Ab_ = As + (c & 1) * CT_AT;
        const float* Vb_ = Vs + (c & 1) * CT_VT;
        if (c + 1 < nk) { A_STS((c + 1) & 1, c + 1); V_STS((c + 1) & 1); }
        if (c + 2 < nk) { A_LDG(c + 2); V_LDG(c + 2); }

#pragma unroll
        for (int kk = 0; kk < 64; kk += 8) {
            uint32_t af[2][4], bf[4][2];
#pragma unroll
            for (int i = 0; i < 2; i++) {
                int r = wm + i * 16 + g;
                af[i][0] = __float_as_uint(Ab_[(r)     * CT_ASTR + kk + a]);
                af[i][1] = __float_as_uint(Ab_[(r + 8) * CT_ASTR + kk + a]);
                af[i][2] = __float_as_uint(Ab_[(r)     * CT_ASTR + kk + 4 + a]);
                af[i][3] = __float_as_uint(Ab_[(r + 8) * CT_ASTR + kk + 4 + a]);
            }
#pragma unroll
            for (int j = 0; j < 4; j++) {
                int n = wn + j * 8 + g;
                bf[j][0] = __float_as_uint(Vb_[(kk + a)     * CT_VSTR + n]);
                bf[j][1] = __float_as_uint(Vb_[(kk + 4 + a) * CT_VSTR + n]);
            }
#pragma unroll
            for (int i = 0; i < 2; i++)
#pragma unroll
                for (int j = 0; j < 4; j++)
                    mma_tf32(acc[i][j], af[i], bf[j]);
        }
        __syncthreads();
    }
#undef A_LDG
#undef A_STS
#undef V_LDG
#undef V_STS

#pragma unroll
    for (int i = 0; i < 2; i++) {
        int row = mt + wm + i * 16 + g;
#pragma unroll
        for (int j = 0; j < 4; j++) {
            int col = wn + j * 8 + a * 2;
            *(float2*)(g_ctx + (size_t)(b * S_ + row) * D_ + h * HD_ + col) =
                make_float2(acc[i][j][0], acc[i][j][1]);
            *(float2*)(g_ctx + (size_t)(b * S_ + row + 8) * D_ + h * HD_ + col) =
                make_float2(acc[i][j][2], acc[i][j][3]);
        }
    }
}

// ---------------------------------------------------------------------------
extern "C" void kernel_launch(void* const* d_in, const int* in_sizes, int n_in,
                              void* d_out, int out_size)
{
    const float* x    = (const float*)d_in[0];
    const float* mask = (const float*)d_in[1];
    const float* Wqkv = (const float*)d_in[2];
    const float* bqkv = (const float*)d_in[3];
    const float* Wo   = (const float*)d_in[4];
    const float* bo   = (const float*)d_in[5];

    float* out = (float*)d_out;                       // [B,S,D]
    float* att = out + (size_t)B_ * S_ * D_;          // [B,H,S,S]

    cudaFuncSetAttribute(scores_kernel,
                         cudaFuncAttributeMaxDynamicSharedMemorySize, SCORES_SMEM);
    cudaFuncSetAttribute(ctx_kernel,
                         cudaFuncAttributeMaxDynamicSharedMemorySize, CTX_SMEM);

    // 1) fused QKV projection
    {
        dim3 grid(QKVN / 128, M_ / 128);
        qkv_gemm_kernel<<<grid, 256>>>(x, Wqkv, bqkv);
    }
    // 2a) e-scores (pre-exponentiated) + half partials
    {
        dim3 grid(S_ / 128, S_ / 128, B_ * H_);
        scores_kernel<<<grid, 256, SCORES_SMEM>>>(mask, att);
    }
    // 2b) ctx = softmax(att) @ V, normalized att written in-flight
    {
        dim3 grid(S_ / 128, B_ * H_);
        ctx_kernel<<<grid, 256, CTX_SMEM>>>(att);
    }
    // 3) output projection
    {
        dim3 grid(D_ / 128, M_ / 128);
        out_gemm_kernel<<<grid, 256>>>(Wo, bo, out);
    }
}

// round 13
// speedup vs baseline: 1.1766x; 1.0378x over previous
#include <cuda_runtime.h>
#include <cstdint>

// Problem constants
#define B_   4
#define S_   1024
#define D_   1024
#define H_   16
#define HD_  64
#define QKVN 3072
#define M_   (B_ * S_)

// Scratch (static device globals — allocation-free per harness rules)
__device__ float g_qkv[(size_t)M_ * QKVN];     // [b,s, h*192 + {q,k,v}*64]
__device__ float g_ctx[(size_t)M_ * D_];       // [b,s, h*64+d]
__device__ float2 g_part[(size_t)B_ * H_ * S_ * 16];  // per (bh,q,chunk64): (max, expsum)

// ---------------------------------------------------------------------------
// helpers
// ---------------------------------------------------------------------------
__device__ __forceinline__ float to_tf32(float x) {
    uint32_t u;
    asm("cvt.rna.tf32.f32 %0, %1;" : "=r"(u) : "f"(x));
    return __uint_as_float(u);
}

__device__ __forceinline__ void mma_tf32(float* d, const uint32_t* a, const uint32_t* b) {
    asm volatile(
        "mma.sync.aligned.m16n8k8.row.col.f32.tf32.tf32.f32 "
        "{%0,%1,%2,%3}, {%4,%5,%6,%7}, {%8,%9}, {%0,%1,%2,%3};\n"
        : "+f"(d[0]), "+f"(d[1]), "+f"(d[2]), "+f"(d[3])
        : "r"(a[0]), "r"(a[1]), "r"(a[2]), "r"(a[3]), "r"(b[0]), "r"(b[1]));
}

// ---------------------------------------------------------------------------
// tf32 GEMM (proven form, FROZEN): 128x128 tile, BK=32, 8 warps (4M x 2N),
// warp tile 32x64, static smem, single buffer.
// ---------------------------------------------------------------------------
#define BK   32
#define ASTR 36
#define BSTR 136

__device__ __forceinline__ void gemm_tf32_body(
    const float* __restrict__ A, const float* __restrict__ Bm,
    const float* __restrict__ bias, float* __restrict__ C,
    int N, int K)
{
    __shared__ float As[128 * ASTR];
    __shared__ float Bs[BK * BSTR];

    const int tid  = threadIdx.x;
    const int lane = tid & 31;
    const int wid  = tid >> 5;
    const int wm   = (wid & 3) * 32;
    const int wn   = (wid >> 2) * 64;
    const int bx   = blockIdx.x * 128;
    const int by   = blockIdx.y * 128;

    const int g = lane >> 2;
    const int a = lane & 3;

    float acc[2][8][4];
#pragma unroll
    for (int i = 0; i < 2; i++)
#pragma unroll
        for (int j = 0; j < 8; j++)
#pragma unroll
            for (int v = 0; v < 4; v++) acc[i][j][v] = 0.f;

    const int arow0 = tid >> 3;
    const int acol  = (tid & 7) * 4;
    const int brow0 = tid >> 5;
    const int bcol  = (tid & 31) * 4;

    for (int k0 = 0; k0 < K; k0 += BK) {
        float4 av[4], bv[4];
#pragma unroll
        for (int i = 0; i < 4; i++)
            av[i] = *(const float4*)(A + (size_t)(by + arow0 + 32 * i) * K + k0 + acol);
#pragma unroll
        for (int i = 0; i < 4; i++)
            bv[i] = *(const float4*)(Bm + (size_t)(k0 + brow0 + 8 * i) * N + bx + bcol);

        __syncthreads();
#pragma unroll
        for (int i = 0; i < 4; i++) {
            float4 t = av[i];
            t.x = to_tf32(t.x); t.y = to_tf32(t.y); t.z = to_tf32(t.z); t.w = to_tf32(t.w);
            *(float4*)(As + (arow0 + 32 * i) * ASTR + acol) = t;
        }
#pragma unroll
        for (int i = 0; i < 4; i++) {
            float4 t = bv[i];
            t.x = to_tf32(t.x); t.y = to_tf32(t.y); t.z = to_tf32(t.z); t.w = to_tf32(t.w);
            *(float4*)(Bs + (brow0 + 8 * i) * BSTR + bcol) = t;
        }
        __syncthreads();

#pragma unroll
        for (int kk = 0; kk < BK; kk += 8) {
            uint32_t af[2][4], bf[8][2];
#pragma unroll
            for (int i = 0; i < 2; i++) {
                int r = wm + i * 16 + g;
                af[i][0] = __float_as_uint(As[(r)     * ASTR + kk + a]);
                af[i][1] = __float_as_uint(As[(r + 8) * ASTR + kk + a]);
                af[i][2] = __float_as_uint(As[(r)     * ASTR + kk + 4 + a]);
                af[i][3] = __float_as_uint(As[(r + 8) * ASTR + kk + 4 + a]);
            }
#pragma unroll
            for (int j = 0; j < 8; j++) {
                int n = wn + j * 8 + g;
                bf[j][0] = __float_as_uint(Bs[(kk + a)     * BSTR + n]);
                bf[j][1] = __float_as_uint(Bs[(kk + 4 + a) * BSTR + n]);
            }
#pragma unroll
            for (int i = 0; i < 2; i++)
#pragma unroll
                for (int j = 0; j < 8; j++)
                    mma_tf32(acc[i][j], af[i], bf[j]);
        }
    }

#pragma unroll
    for (int i = 0; i < 2; i++) {
        int row = by + wm + i * 16 + g;
#pragma unroll
        for (int j = 0; j < 8; j++) {
            int col = bx + wn + j * 8 + a * 2;
            float b0 = bias[col], b1 = bias[col + 1];
            *(float2*)(C + (size_t)row * N + col) =
                make_float2(acc[i][j][0] + b0, acc[i][j][1] + b1);
            *(float2*)(C + (size_t)(row + 8) * N + col) =
                make_float2(acc[i][j][2] + b0, acc[i][j][3] + b1);
        }
    }
}

__global__ __launch_bounds__(256) void qkv_gemm_kernel(
    const float* __restrict__ x, const float* __restrict__ W,
    const float* __restrict__ bias)
{
    gemm_tf32_body(x, W, bias, g_qkv, QKVN, D_);
}

__global__ __launch_bounds__(256) void out_gemm_kernel(
    const float* __restrict__ W, const float* __restrict__ bias,
    float* __restrict__ out)
{
    gemm_tf32_body(g_ctx, W, bias, out, D_, D_);
}

// ---------------------------------------------------------------------------
// scores kernel (FROZEN from R12): s = (Q*0.125)K^T + mask; writes
// e = exp(s - m_half) to att and per-(row, half64) partials to g_part.
// ---------------------------------------------------------------------------
#define SC_STR 68
#define SCORES_SMEM ((128 * SC_STR * 2) * 4)

__global__ __launch_bounds__(256) void scores_kernel(
    const float* __restrict__ mask, float* __restrict__ att)
{
    extern __shared__ float sms[];
    float* Qs = sms;
    float* Ks = sms + 128 * SC_STR;

    const int bh = blockIdx.z;
    const int b  = bh >> 4, h = bh & 15;
    const int qt = blockIdx.y * 128;
    const int kt = blockIdx.x * 128;
    const int tid = threadIdx.x;
    const int lane = tid & 31, w = tid >> 5;
    const int g = lane >> 2, a = lane & 3;
    const int wm = (w & 3) * 32, wn = (w >> 2) * 64;

    const float* qkv_b = g_qkv + (size_t)(b * S_) * QKVN + h * 192;

    {
        int row = tid >> 4;
        int c4  = (tid & 15) * 4;
#pragma unroll
        for (int i = 0; i < 8; i++) {
            float4 t = *(const float4*)(qkv_b + (size_t)(qt + row + 16 * i) * QKVN + c4);
            t.x = to_tf32(t.x * 0.125f); t.y = to_tf32(t.y * 0.125f);
            t.z = to_tf32(t.z * 0.125f); t.w = to_tf32(t.w * 0.125f);
            *(float4*)(Qs + (row + 16 * i) * SC_STR + c4) = t;
        }
#pragma unroll
        for (int i = 0; i < 8; i++) {
            float4 t = *(const float4*)(qkv_b + (size_t)(kt + row + 16 * i) * QKVN + 64 + c4);
            t.x = to_tf32(t.x); t.y = to_tf32(t.y); t.z = to_tf32(t.z); t.w = to_tf32(t.w);
            *(float4*)(Ks + (row + 16 * i) * SC_STR + c4) = t;
        }
    }
    __syncthreads();

    float acc[2][8][4];
#pragma unroll
    for (int i = 0; i < 2; i++)
#pragma unroll
        for (int j = 0; j < 8; j++)
#pragma unroll
            for (int v = 0; v < 4; v++) acc[i][j][v] = 0.f;

#pragma unroll
    for (int ks = 0; ks < 8; ks++) {
        int k0 = ks * 8;
        uint32_t af[2][4], bf[8][2];
#pragma unroll
        for (int i = 0; i < 2; i++) {
            int r = wm + i * 16 + g;
            af[i][0] = __float_as_uint(Qs[(r)     * SC_STR + k0 + a]);
            af[i][1] = __float_as_uint(Qs[(r + 8) * SC_STR + k0 + a]);
            af[i][2] = __float_as_uint(Qs[(r)     * SC_STR + k0 + 4 + a]);
            af[i][3] = __float_as_uint(Qs[(r + 8) * SC_STR + k0 + 4 + a]);
        }
#pragma unroll
        for (int j = 0; j < 8; j++) {
            int n = wn + j * 8 + g;
            bf[j][0] = __float_as_uint(Ks[n * SC_STR + k0 + a]);
            bf[j][1] = __float_as_uint(Ks[n * SC_STR + k0 + 4 + a]);
        }
#pragma unroll
        for (int i = 0; i < 2; i++)
#pragma unroll
            for (int j = 0; j < 8; j++)
                mma_tf32(acc[i][j], af[i], bf[j]);
    }

    float* abase = att + ((size_t)(b * H_ + h) * S_ + qt) * S_ + kt;
    const float* mbase = mask + ((size_t)(b * S_) + qt) * S_ + kt;
    const int half = wn >> 6;
#pragma unroll
    for (int i = 0; i < 2; i++) {
        int r0 = wm + i * 16 + g;
        float mx0 = -1e30f, mx1 = -1e30f;
#pragma unroll
        for (int j = 0; j < 8; j++) {
            int col = wn + j * 8 + a * 2;
            float2 m0 = *(const float2*)(mbase + (size_t)r0 * S_ + col);
            float2 m1 = *(const float2*)(mbase + (size_t)(r0 + 8) * S_ + col);
            acc[i][j][0] += m0.x; acc[i][j][1] += m0.y;
            acc[i][j][2] += m1.x; acc[i][j][3] += m1.y;
            mx0 = fmaxf(mx0, fmaxf(acc[i][j][0], acc[i][j][1]));
            mx1 = fmaxf(mx1, fmaxf(acc[i][j][2], acc[i][j][3]));
        }
        mx0 = fmaxf(mx0, __shfl_xor_sync(~0u, mx0, 1));
        mx0 = fmaxf(mx0, __shfl_xor_sync(~0u, mx0, 2));
        mx1 = fmaxf(mx1, __shfl_xor_sync(~0u, mx1, 1));
        mx1 = fmaxf(mx1, __shfl_xor_sync(~0u, mx1, 2));
        float s0 = 0.f, s1 = 0.f;
#pragma unroll
        for (int j = 0; j < 8; j++) {
            int col = wn + j * 8 + a * 2;
            float e00 = __expf(acc[i][j][0] - mx0);
            float e01 = __expf(acc[i][j][1] - mx0);
            float e10 = __expf(acc[i][j][2] - mx1);
            float e11 = __expf(acc[i][j][3] - mx1);
            s0 += e00 + e01;
            s1 += e10 + e11;
            *(float2*)(abase + (size_t)r0 * S_ + col)       = make_float2(e00, e01);
            *(float2*)(abase + (size_t)(r0 + 8) * S_ + col) = make_float2(e10, e11);
        }
        s0 += __shfl_xor_sync(~0u, s0, 1); s0 += __shfl_xor_sync(~0u, s0, 2);
        s1 += __shfl_xor_sync(~0u, s1, 1); s1 += __shfl_xor_sync(~0u, s1, 2);
        if (a == 0) {
            g_part[((size_t)bh * S_ + qt + r0)     * 16 + blockIdx.x * 2 + half] =
                make_float2(mx0, s0);
            g_part[((size_t)bh * S_ + qt + r0 + 8) * 16 + blockIdx.x * 2 + half] =
                make_float2(mx1, s1);
        }
    }
}

// ---------------------------------------------------------------------------
// ctx kernel: prologue builds the FULL per-(chunk,row) scale table
// scale[c][row] = exp(m_c - M)/S in smem (one pass over g_part, 16 exps/row).
// Steady loop: A_STS = e * scale (1 broadcast LDS + 4 FMUL per float4);
// writes normalized att; computes g_ctx = P @ V.  Grid/tiling as R9.
// ---------------------------------------------------------------------------
#define CT_ASTR 68
#define CT_VSTR 72
#define CT_AT   (128 * CT_ASTR)
#define CT_VT   (64 * CT_VSTR)
#define CTX_SMEM (2 * (CT_AT + CT_VT) * 4)

__global__ __launch_bounds__(256) void ctx_kernel(float* __restrict__ att)
{
    extern __shared__ float smcx[];
    float* As = smcx;
    float* Vs = smcx + 2 * CT_AT;
    __shared__ float sm_scale[16][128];   // [chunk64][row]

    const int bh = blockIdx.y;
    const int b  = bh >> 4, h = bh & 15;
    const int mt = blockIdx.x * 128;
    const int tid = threadIdx.x;
    const int lane = tid & 31, w = tid >> 5;
    const int g = lane >> 2, a = lane & 3;
    const int wm = (w & 3) * 32, wn = (w >> 2) * 32;

    float* abase = att + ((size_t)bh * S_ + mt) * S_;
    const float* vbase = g_qkv + (size_t)(b * S_) * QKVN + h * 192 + 128;

    const int lrow = tid >> 4;
    const int lc4  = (tid & 15) * 4;

    // prologue: combine 16 partials -> exact row (M, 1/S) -> scale table
    if (tid < 128) {
        const float2* pp = g_part + ((size_t)bh * S_ + mt + tid) * 16;
        float2 t[16];
#pragma unroll
        for (int k = 0; k < 16; k++) t[k] = pp[k];
        float M = t[0].x;
#pragma unroll
        for (int k = 1; k < 16; k++) M = fmaxf(M, t[k].x);
        float es[16];
        float S = 0.f;
#pragma unroll
        for (int k = 0; k < 16; k++) {
            es[k] = __expf(t[k].x - M);
            S += t[k].y * es[k];
        }
        float inv = 1.f / S;
#pragma unroll
        for (int k = 0; k < 16; k++) sm_scale[k][tid] = es[k] * inv;
    }
    __syncthreads();

    float4 avr[8], bvr[4];

#define A_LDG(c)                                                               \
    {                                                                          \
        _Pragma("unroll")                                                      \
        for (int i = 0; i < 8; i++)                                            \
            avr[i] = *(const float4*)(abase + (size_t)(lrow + 16 * i) * S_ +   \
                                      (c) * 64 + lc4);                         \
    }
    // rescale e-values by per-(chunk,row) factor + write normalized att + stage
#define A_STS(buf, c)                                                          \
    {                                                                          \
        float* dst = As + (buf) * CT_AT;                                       \
        _Pragma("unroll")                                                      \
        for (int i = 0; i < 8; i++) {                                          \
            float sc_i = sm_scale[c][lrow + 16 * i];                           \
            float4 t = avr[i];                                                 \
            t.x *= sc_i; t.y *= sc_i; t.z *= sc_i; t.w *= sc_i;                \
            *(float4*)(abase + (size_t)(lrow + 16 * i) * S_ + (c) * 64 + lc4) = t; \
            t.x = to_tf32(t.x); t.y = to_tf32(t.y);                            \
            t.z = to_tf32(t.z); t.w = to_tf32(t.w);                            \
            *(float4*)(dst + (lrow + 16 * i) * CT_ASTR + lc4) = t;             \
        }                                                                      \
    }
#define V_LDG(c)                                                               \
    {                                                                          \
        _Pragma("unroll")                                                      \
        for (int i = 0; i < 4; i++)                                            \
            bvr[i] = *(const float4*)(vbase +                                  \
                (size_t)((c) * 64 + lrow + 16 * i) * QKVN + lc4);              \
    }
#define V_STS(buf)                                                             \
    {                                                                          \
        float* dst = Vs + (buf) * CT_VT;                                       \
        _Pragma("unroll")                                                      \
        for (int i = 0; i < 4; i++) {                                          \
            float4 t = bvr[i];                                                 \
            t.x = to_tf32(t.x); t.y = to_tf32(t.y);                            \
            t.z = to_tf32(t.z); t.w = to_tf32(t.w);                            \
            *(float4*)(dst + (lrow + 16 * i) * CT_VSTR + lc4) = t;             \
        }                                                                      \
    }

    float acc[2][4][4];
#pragma unroll
    for (int i = 0; i < 2; i++)
#pragma unroll
        for (int j = 0; j < 4; j++)
#pragma unroll
            for (int v = 0; v < 4; v++) acc[i][j][v] = 0.f;

    const int nk = S_ / 64;
    A_LDG(0); A_STS(0, 0);
    V_LDG(0); V_STS(0);
    A_LDG(1); V_LDG(1);
    __syncthreads();

    for (int c = 0; c < nk; c++) {
        const float* Ab_ = As + (c & 1) * CT_AT;
        const float* Vb_ = Vs + (c & 1) * CT_VT;
        if (c + 1 < nk) { A_STS((c + 1) & 1, c + 1); V_STS((c + 1) & 1); }
        if (c + 2 < nk) { A_LDG(c + 2); V_LDG(c + 2); }

#pragma unroll
        for (int kk = 0; kk < 64; kk += 8) {
            uint32_t af[2][4], bf[4][2];
#pragma unroll
            for (int i = 0; i < 2; i++) {
                int r = wm + i * 16 + g;
                af[i][0] = __float_as_uint(Ab_[(r)     * CT_ASTR + kk + a]);
                af[i][1] = __float_as_uint(Ab_[(r + 8) * CT_ASTR + kk + a]);
                af[i][2] = __float_as_uint(Ab_[(r)     * CT_ASTR + kk + 4 + a]);
                af[i][3] = __float_as_uint(Ab_[(r + 8) * CT_ASTR + kk + 4 + a]);
            }
#pragma unroll
            for (int j = 0; j < 4; j++) {
                int n = wn + j * 8 + g;
                bf[j][0] = __float_as_uint(Vb_[(kk + a)     * CT_VSTR + n]);
                bf[j][1] = __float_as_uint(Vb_[(kk + 4 + a) * CT_VSTR + n]);
            }
#pragma unroll
            for (int i = 0; i < 2; i++)
#pragma unroll
                for (int j = 0; j < 4; j++)
                    mma_tf32(acc[i][j], af[i], bf[j]);
        }
        __syncthreads();
    }
#undef A_LDG
#undef A_STS
#undef V_LDG
#undef V_STS

#pragma unroll
    for (int i = 0; i < 2; i++) {
        int row = mt + wm + i * 16 + g;
#pragma unroll
        for (int j = 0; j < 4; j++) {
            int col = wn + j * 8 + a * 2;
            *(float2*)(g_ctx + (size_t)(b * S_ + row) * D_ + h * HD_ + col) =
                make_float2(acc[i][j][0], acc[i][j][1]);
            *(float2*)(g_ctx + (size_t)(b * S_ + row + 8) * D_ + h * HD_ + col) =
                make_float2(acc[i][j][2], acc[i][j][3]);
        }
    }
}

// ---------------------------------------------------------------------------
extern "C" void kernel_launch(void* const* d_in, const int* in_sizes, int n_in,
                              void* d_out, int out_size)
{
    const float* x    = (const float*)d_in[0];
    const float* mask = (const float*)d_in[1];
    const float* Wqkv = (const float*)d_in[2];
    const float* bqkv = (const float*)d_in[3];
    const float* Wo   = (const float*)d_in[4];
    const float* bo   = (const float*)d_in[5];

    float* out = (float*)d_out;                       // [B,S,D]
    float* att = out + (size_t)B_ * S_ * D_;          // [B,H,S,S]

    cudaFuncSetAttribute(scores_kernel,
                         cudaFuncAttributeMaxDynamicSharedMemorySize, SCORES_SMEM);
    cudaFuncSetAttribute(ctx_kernel,
                         cudaFuncAttributeMaxDynamicSharedMemorySize, CTX_SMEM);

    // 1) fused QKV projection
    {
        dim3 grid(QKVN / 128, M_ / 128);
        qkv_gemm_kernel<<<grid, 256>>>(x, Wqkv, bqkv);
    }
    // 2a) e-scores (pre-exponentiated) + half partials
    {
        dim3 grid(S_ / 128, S_ / 128, B_ * H_);
        scores_kernel<<<grid, 256, SCORES_SMEM>>>(mask, att);
    }
    // 2b) ctx = softmax(att) @ V via smem scale table, att normalized in-flight
    {
        dim3 grid(S_ / 128, B_ * H_);
        ctx_kernel<<<grid, 256, CTX_SMEM>>>(att);
    }
    // 3) output projection
    {
        dim3 grid(D_ / 128, M_ / 128);
        out_gemm_kernel<<<grid, 256>>>(Wo, bo, out);
    }
}

// round 14
// speedup vs baseline: 1.1929x; 1.0139x over previous
#include <cuda_runtime.h>
#include <cstdint>

// Problem constants
#define B_   4
#define S_   1024
#define D_   1024
#define H_   16
#define HD_  64
#define QKVN 3072
#define M_   (B_ * S_)

// Scratch (static device globals — allocation-free per harness rules)
__device__ float g_qkv[(size_t)M_ * QKVN];     // [b,s, h*192 + {q,k,v}*64]
__device__ float g_ctx[(size_t)M_ * D_];       // [b,s, h*64+d]
__device__ float2 g_part[(size_t)B_ * H_ * S_ * 16];  // per (bh,q,chunk64): (max, expsum)
__device__ float g_wt[(size_t)QKVN * D_];      // Wqkv^T : [n][k]
__device__ float g_wot[(size_t)D_ * D_];       // Wo^T   : [n][k]

// ---------------------------------------------------------------------------
// helpers
// ---------------------------------------------------------------------------
__device__ __forceinline__ float to_tf32(float x) {
    uint32_t u;
    asm("cvt.rna.tf32.f32 %0, %1;" : "=r"(u) : "f"(x));
    return __uint_as_float(u);
}

__device__ __forceinline__ void mma_tf32(float* d, const uint32_t* a, const uint32_t* b) {
    asm volatile(
        "mma.sync.aligned.m16n8k8.row.col.f32.tf32.tf32.f32 "
        "{%0,%1,%2,%3}, {%4,%5,%6,%7}, {%8,%9}, {%0,%1,%2,%3};\n"
        : "+f"(d[0]), "+f"(d[1]), "+f"(d[2]), "+f"(d[3])
        : "r"(a[0]), "r"(a[1]), "r"(a[2]), "r"(a[3]), "r"(b[0]), "r"(b[1]));
}

__device__ __forceinline__ void ldsm_x4(uint32_t& r0, uint32_t& r1,
                                        uint32_t& r2, uint32_t& r3, uint32_t addr) {
    asm volatile("ldmatrix.sync.aligned.m8n8.x4.shared.b16 {%0,%1,%2,%3}, [%4];"
                 : "=r"(r0), "=r"(r1), "=r"(r2), "=r"(r3) : "r"(addr));
}

// ---------------------------------------------------------------------------
// transpose: Wt[n][k] = W[k][n]  (W is [K][N] row-major); dst selected by flag
// ---------------------------------------------------------------------------
__global__ __launch_bounds__(256) void transpose_kernel(
    const float* __restrict__ W, int N, int K, int dst_sel)
{
    float* Wt = dst_sel ? g_wot : g_wt;
    __shared__ float t[32][33];
    const int n0 = blockIdx.x * 32, k0 = blockIdx.y * 32;
    const int tx = threadIdx.x & 31, ty = threadIdx.x >> 5;  // 32 x 8
#pragma unroll
    for (int i = 0; i < 4; i++)
        t[ty + 8 * i][tx] = W[(size_t)(k0 + ty + 8 * i) * N + n0 + tx];
    __syncthreads();
#pragma unroll
    for (int i = 0; i < 4; i++)
        Wt[(size_t)(n0 + ty + 8 * i) * K + k0 + tx] = t[tx][ty + 8 * i];
}

// ---------------------------------------------------------------------------
// tf32 GEMM with ldmatrix fragment feeds.
// C[M x N] = A[M x K] @ Bt[N x K]^T + bias.  128x128 tile, BK=32,
// 8 warps (4M x 2N), warp tile 32x64.  Both tiles [row][k] stride 36
// (rows at banks 4r..4r+3 -> ldmatrix conflict-free; float4 STS staging CF).
// Per kk: 2 LDSM.x4 (A) + 4 LDSM.x4 (B) + 16 MMA  (was 24 scalar LDS).
// ---------------------------------------------------------------------------
#define BK   32
#define TSTR 36

__device__ __forceinline__ void gemm_lds_body(
    const float* __restrict__ A, const float* __restrict__ Bt,
    const float* __restrict__ bias, float* __restrict__ C,
    int N, int K)
{
    __shared__ float As[128 * TSTR];
    __shared__ float Bs[128 * TSTR];

    const int tid  = threadIdx.x;
    const int lane = tid & 31;
    const int wid  = tid >> 5;
    const int wm   = (wid & 3) * 32;
    const int wn   = (wid >> 2) * 64;
    const int bx   = blockIdx.x * 128;
    const int by   = blockIdx.y * 128;

    const int g = lane >> 2;
    const int a = lane & 3;

    float acc[2][8][4];
#pragma unroll
    for (int i = 0; i < 2; i++)
#pragma unroll
        for (int j = 0; j < 8; j++)
#pragma unroll
            for (int v = 0; v < 4; v++) acc[i][j][v] = 0.f;

    // staging geometry (both tiles identical): 128 rows x 32 k
    const int srow = tid >> 3;          // 0..31 (+32*i)
    const int scol = (tid & 7) * 4;     // 0..28

    // ldmatrix per-lane base offsets (floats)
    const uint32_t as_base = (uint32_t)__cvta_generic_to_shared(As);
    const uint32_t bs_base = (uint32_t)__cvta_generic_to_shared(Bs);
    uint32_t aoff[2], boff[4];
#pragma unroll
    for (int i = 0; i < 2; i++)
        aoff[i] = as_base +
            ((wm + i * 16 + ((lane >> 3) & 1) * 8 + (lane & 7)) * TSTR
             + (lane >> 4) * 4) * 4;
#pragma unroll
    for (int jj = 0; jj < 4; jj++)
        boff[jj] = bs_base +
            ((wn + 8 * (2 * jj + (lane >> 4)) + (lane & 7)) * TSTR
             + ((lane >> 3) & 1) * 4) * 4;

    for (int k0 = 0; k0 < K; k0 += BK) {
        float4 av[4], bv[4];
#pragma unroll
        for (int i = 0; i < 4; i++)
            av[i] = *(const float4*)(A + (size_t)(by + srow + 32 * i) * K + k0 + scol);
#pragma unroll
        for (int i = 0; i < 4; i++)
            bv[i] = *(const float4*)(Bt + (size_t)(bx + srow + 32 * i) * K + k0 + scol);

        __syncthreads();
#pragma unroll
        for (int i = 0; i < 4; i++) {
            float4 t = av[i];
            t.x = to_tf32(t.x); t.y = to_tf32(t.y); t.z = to_tf32(t.z); t.w = to_tf32(t.w);
            *(float4*)(As + (srow + 32 * i) * TSTR + scol) = t;
        }
#pragma unroll
        for (int i = 0; i < 4; i++) {
            float4 t = bv[i];
            t.x = to_tf32(t.x); t.y = to_tf32(t.y); t.z = to_tf32(t.z); t.w = to_tf32(t.w);
            *(float4*)(Bs + (srow + 32 * i) * TSTR + scol) = t;
        }
        __syncthreads();

#pragma unroll
        for (int kk = 0; kk < BK; kk += 8) {
            uint32_t af[2][4], bf[8][2];
#pragma unroll
            for (int i = 0; i < 2; i++)
                ldsm_x4(af[i][0], af[i][1], af[i][2], af[i][3], aoff[i] + kk * 4);
#pragma unroll
            for (int jj = 0; jj < 4; jj++)
                ldsm_x4(bf[2 * jj][0], bf[2 * jj][1],
                        bf[2 * jj + 1][0], bf[2 * jj + 1][1], boff[jj] + kk * 4);
#pragma unroll
            for (int i = 0; i < 2; i++)
#pragma unroll
                for (int j = 0; j < 8; j++)
                    mma_tf32(acc[i][j], af[i], bf[j]);
        }
    }

#pragma unroll
    for (int i = 0; i < 2; i++) {
        int row = by + wm + i * 16 + g;
#pragma unroll
        for (int j = 0; j < 8; j++) {
            int col = bx + wn + j * 8 + a * 2;
            float b0 = bias[col], b1 = bias[col + 1];
            *(float2*)(C + (size_t)row * N + col) =
                make_float2(acc[i][j][0] + b0, acc[i][j][1] + b1);
            *(float2*)(C + (size_t)(row + 8) * N + col) =
                make_float2(acc[i][j][2] + b0, acc[i][j][3] + b1);
        }
    }
}

__global__ __launch_bounds__(256) void qkv_gemm_kernel(
    const float* __restrict__ x, const float* __restrict__ bias)
{
    gemm_lds_body(x, g_wt, bias, g_qkv, QKVN, D_);
}

__global__ __launch_bounds__(256) void out_gemm_kernel(
    const float* __restrict__ bias, float* __restrict__ out)
{
    gemm_lds_body(g_ctx, g_wot, bias, out, D_, D_);
}

// ---------------------------------------------------------------------------
// scores kernel (FROZEN from R12/R13): s = (Q*0.125)K^T + mask; writes
// e = exp(s - m_half) to att and per-(row, half64) partials to g_part.
// ---------------------------------------------------------------------------
#define SC_STR 68
#define SCORES_SMEM ((128 * SC_STR * 2) * 4)

__global__ __launch_bounds__(256) void scores_kernel(
    const float* __restrict__ mask, float* __restrict__ att)
{
    extern __shared__ float sms[];
    float* Qs = sms;
    float* Ks = sms + 128 * SC_STR;

    const int bh = blockIdx.z;
    const int b  = bh >> 4, h = bh & 15;
    const int qt = blockIdx.y * 128;
    const int kt = blockIdx.x * 128;
    const int tid = threadIdx.x;
    const int lane = tid & 31, w = tid >> 5;
    const int g = lane >> 2, a = lane & 3;
    const int wm = (w & 3) * 32, wn = (w >> 2) * 64;

    const float* qkv_b = g_qkv + (size_t)(b * S_) * QKVN + h * 192;

    {
        int row = tid >> 4;
        int c4  = (tid & 15) * 4;
#pragma unroll
        for (int i = 0; i < 8; i++) {
            float4 t = *(const float4*)(qkv_b + (size_t)(qt + row + 16 * i) * QKVN + c4);
            t.x = to_tf32(t.x * 0.125f); t.y = to_tf32(t.y * 0.125f);
            t.z = to_tf32(t.z * 0.125f); t.w = to_tf32(t.w * 0.125f);
            *(float4*)(Qs + (row + 16 * i) * SC_STR + c4) = t;
        }
#pragma unroll
        for (int i = 0; i < 8; i++) {
            float4 t = *(const float4*)(qkv_b + (size_t)(kt + row + 16 * i) * QKVN + 64 + c4);
            t.x = to_tf32(t.x); t.y = to_tf32(t.y); t.z = to_tf32(t.z); t.w = to_tf32(t.w);
            *(float4*)(Ks + (row + 16 * i) * SC_STR + c4) = t;
        }
    }
    __syncthreads();

    float acc[2][8][4];
#pragma unroll
    for (int i = 0; i < 2; i++)
#pragma unroll
        for (int j = 0; j < 8; j++)
#pragma unroll
            for (int v = 0; v < 4; v++) acc[i][j][v] = 0.f;

#pragma unroll
    for (int ks = 0; ks < 8; ks++) {
        int k0 = ks * 8;
        uint32_t af[2][4], bf[8][2];
#pragma unroll
        for (int i = 0; i < 2; i++) {
            int r = wm + i * 16 + g;
            af[i][0] = __float_as_uint(Qs[(r)     * SC_STR + k0 + a]);
            af[i][1] = __float_as_uint(Qs[(r + 8) * SC_STR + k0 + a]);
            af[i][2] = __float_as_uint(Qs[(r)     * SC_STR + k0 + 4 + a]);
            af[i][3] = __float_as_uint(Qs[(r + 8) * SC_STR + k0 + 4 + a]);
        }
#pragma unroll
        for (int j = 0; j < 8; j++) {
            int n = wn + j * 8 + g;
            bf[j][0] = __float_as_uint(Ks[n * SC_STR + k0 + a]);
            bf[j][1] = __float_as_uint(Ks[n * SC_STR + k0 + 4 + a]);
        }
#pragma unroll
        for (int i = 0; i < 2; i++)
#pragma unroll
            for (int j = 0; j < 8; j++)
                mma_tf32(acc[i][j], af[i], bf[j]);
    }

    float* abase = att + ((size_t)(b * H_ + h) * S_ + qt) * S_ + kt;
    const float* mbase = mask + ((size_t)(b * S_) + qt) * S_ + kt;
    const int half = wn >> 6;
#pragma unroll
    for (int i = 0; i < 2; i++) {
        int r0 = wm + i * 16 + g;
        float mx0 = -1e30f, mx1 = -1e30f;
#pragma unroll
        for (int j = 0; j < 8; j++) {
            int col = wn + j * 8 + a * 2;
            float2 m0 = *(const float2*)(mbase + (size_t)r0 * S_ + col);
            float2 m1 = *(const float2*)(mbase + (size_t)(r0 + 8) * S_ + col);
            acc[i][j][0] += m0.x; acc[i][j][1] += m0.y;
            acc[i][j][2] += m1.x; acc[i][j][3] += m1.y;
            mx0 = fmaxf(mx0, fmaxf(acc[i][j][0], acc[i][j][1]));
            mx1 = fmaxf(mx1, fmaxf(acc[i][j][2], acc[i][j][3]));
        }
        mx0 = fmaxf(mx0, __shfl_xor_sync(~0u, mx0, 1));
        mx0 = fmaxf(mx0, __shfl_xor_sync(~0u, mx0, 2));
        mx1 = fmaxf(mx1, __shfl_xor_sync(~0u, mx1, 1));
        mx1 = fmaxf(mx1, __shfl_xor_sync(~0u, mx1, 2));
        float s0 = 0.f, s1 = 0.f;
#pragma unroll
        for (int j = 0; j < 8; j++) {
            int col = wn + j * 8 + a * 2;
            float e00 = __expf(acc[i][j][0] - mx0);
            float e01 = __expf(acc[i][j][1] - mx0);
            float e10 = __expf(acc[i][j][2] - mx1);
            float e11 = __expf(acc[i][j][3] - mx1);
            s0 += e00 + e01;
            s1 += e10 + e11;
            *(float2*)(abase + (size_t)r0 * S_ + col)       = make_float2(e00, e01);
            *(float2*)(abase + (size_t)(r0 + 8) * S_ + col) = make_float2(e10, e11);
        }
        s0 += __shfl_xor_sync(~0u, s0, 1); s0 += __shfl_xor_sync(~0u, s0, 2);
        s1 += __shfl_xor_sync(~0u, s1, 1); s1 += __shfl_xor_sync(~0u, s1, 2);
        if (a == 0) {
            g_part[((size_t)bh * S_ + qt + r0)     * 16 + blockIdx.x * 2 + half] =
                make_float2(mx0, s0);
            g_part[((size_t)bh * S_ + qt + r0 + 8) * 16 + blockIdx.x * 2 + half] =
                make_float2(mx1, s1);
        }
    }
}

// ---------------------------------------------------------------------------
// ctx kernel (FROZEN from R13): smem scale table + P@V, att normalized in-flight
// ---------------------------------------------------------------------------
#define CT_ASTR 68
#define CT_VSTR 72
#define CT_AT   (128 * CT_ASTR)
#define CT_VT   (64 * CT_VSTR)
#define CTX_SMEM (2 * (CT_AT + CT_VT) * 4)

__global__ __launch_bounds__(256) void ctx_kernel(float* __restrict__ att)
{
    extern __shared__ float smcx[];
    float* As = smcx;
    float* Vs = smcx + 2 * CT_AT;
    __shared__ float sm_scale[16][128];   // [chunk64][row]

    const int bh = blockIdx.y;
    const int b  = bh >> 4, h = bh & 15;
    const int mt = blockIdx.x * 128;
    const int tid = threadIdx.x;
    const int lane = tid & 31, w = tid >> 5;
    const int g = lane >> 2, a = lane & 3;
    const int wm = (w & 3) * 32, wn = (w >> 2) * 32;

    float* abase = att + ((size_t)bh * S_ + mt) * S_;
    const float* vbase = g_qkv + (size_t)(b * S_) * QKVN + h * 192 + 128;

    const int lrow = tid >> 4;
    const int lc4  = (tid & 15) * 4;

    if (tid < 128) {
        const float2* pp = g_part + ((size_t)bh * S_ + mt + tid) * 16;
        float2 t[16];
#pragma unroll
        for (int k = 0; k < 16; k++) t[k] = pp[k];
        float M = t[0].x;
#pragma unroll
        for (int k = 1; k < 16; k++) M = fmaxf(M, t[k].x);
        float es[16];
        float S = 0.f;
#pragma unroll
        for (int k = 0; k < 16; k++) {
            es[k] = __expf(t[k].x - M);
            S += t[k].y * es[k];
        }
        float inv = 1.f / S;
#pragma unroll
        for (int k = 0; k < 16; k++) sm_scale[k][tid] = es[k] * inv;
    }
    __syncthreads();

    float4 avr[8], bvr[4];

#define A_LDG(c)                                                               \
    {                                                                          \
        _Pragma("unroll")                                                      \
        for (int i = 0; i < 8; i++)                                            \
            avr[i] = *(const float4*)(abase + (size_t)(lrow + 16 * i) * S_ +   \
                                      (c) * 64 + lc4);                         \
    }
#define A_STS(buf, c)                                                          \
    {                                                                          \
        float* dst = As + (buf) * CT_AT;                                       \
        _Pragma("unroll")                                                      \
        for (int i = 0; i < 8; i++) {                                          \
            float sc_i = sm_scale[c][lrow + 16 * i];                           \
            float4 t = avr[i];                                                 \
            t.x *= sc_i; t.y *= sc_i; t.z *= sc_i; t.w *= sc_i;                \
            *(float4*)(abase + (size_t)(lrow + 16 * i) * S_ + (c) * 64 + lc4) = t; \
            t.x = to_tf32(t.x); t.y = to_tf32(t.y);                            \
            t.z = to_tf32(t.z); t.w = to_tf32(t.w);                            \
            *(float4*)(dst + (lrow + 16 * i) * CT_ASTR + lc4) = t;             \
        }                                                                      \
    }
#define V_LDG(c)                                                               \
    {                                                                          \
        _Pragma("unroll")                                                      \
        for (int i = 0; i < 4; i++)                                            \
            bvr[i] = *(const float4*)(vbase +                                  \
                (size_t)((c) * 64 + lrow + 16 * i) * QKVN + lc4);              \
    }
#define V_STS(buf)                                                             \
    {                                                                          \
        float* dst = Vs + (buf) * CT_VT;                                       \
        _Pragma("unroll")                                                      \
        for (int i = 0; i < 4; i++) {                                          \
            float4 t = bvr[i];                                                 \
            t.x = to_tf32(t.x); t.y = to_tf32(t.y);                            \
            t.z = to_tf32(t.z); t.w = to_tf32(t.w);                            \
            *(float4*)(dst + (lrow + 16 * i) * CT_VSTR + lc4) = t;             \
        }                                                                      \
    }

    float acc[2][4][4];
#pragma unroll
    for (int i = 0; i < 2; i++)
#pragma unroll
        for (int j = 0; j < 4; j++)
#pragma unroll
            for (int v = 0; v < 4; v++) acc[i][j][v] = 0.f;

    const int nk = S_ / 64;
    A_LDG(0); A_STS(0, 0);
    V_LDG(0); V_STS(0);
    A_LDG(1); V_LDG(1);
    __syncthreads();

    for (int c = 0; c < nk; c++) {
        const float* Ab_ = As + (c & 1) * CT_AT;
        const float* Vb_ = Vs + (c & 1) * CT_VT;
        if (c + 1 < nk) { A_STS((c + 1) & 1, c + 1); V_STS((c + 1) & 1); }
        if (c + 2 < nk) { A_LDG(c + 2); V_LDG(c + 2); }

#pragma unroll
        for (int kk = 0; kk < 64; kk += 8) {
            uint32_t af[2][4], bf[4][2];
#pragma unroll
            for (int i = 0; i < 2; i++) {
                int r = wm + i * 16 + g;
                af[i][0] = __float_as_uint(Ab_[(r)     * CT_ASTR + kk + a]);
                af[i][1] = __float_as_uint(Ab_[(r + 8) * CT_ASTR + kk + a]);
                af[i][2] = __float_as_uint(Ab_[(r)     * CT_ASTR + kk + 4 + a]);
                af[i][3] = __float_as_uint(Ab_[(r + 8) * CT_ASTR + kk + 4 + a]);
            }
#pragma unroll
            for (int j = 0; j < 4; j++) {
                int n = wn + j * 8 + g;
                bf[j][0] = __float_as_uint(Vb_[(kk + a)     * CT_VSTR + n]);
                bf[j][1] = __float_as_uint(Vb_[(kk + 4 + a) * CT_VSTR + n]);
            }
#pragma unroll
            for (int i = 0; i < 2; i++)
#pragma unroll
                for (int j = 0; j < 4; j++)
                    mma_tf32(acc[i][j], af[i], bf[j]);
        }
        __syncthreads();
    }
#undef A_LDG
#undef A_STS
#undef V_LDG
#undef V_STS

#pragma unroll
    for (int i = 0; i < 2; i++) {
        int row = mt + wm + i * 16 + g;
#pragma unroll
        for (int j = 0; j < 4; j++) {
            int col = wn + j * 8 + a * 2;
            *(float2*)(g_ctx + (size_t)(b * S_ + row) * D_ + h * HD_ + col) =
                make_float2(acc[i][j][0], acc[i][j][1]);
            *(float2*)(g_ctx + (size_t)(b * S_ + row + 8) * D_ + h * HD_ + col) =
                make_float2(acc[i][j][2], acc[i][j][3]);
        }
    }
}

// ---------------------------------------------------------------------------
extern "C" void kernel_launch(void* const* d_in, const int* in_sizes, int n_in,
                              void* d_out, int out_size)
{
    const float* x    = (const float*)d_in[0];
    const float* mask = (const float*)d_in[1];
    const float* Wqkv = (const float*)d_in[2];
    const float* bqkv = (const float*)d_in[3];
    const float* Wo   = (const float*)d_in[4];
    const float* bo   = (const float*)d_in[5];

    float* out = (float*)d_out;                       // [B,S,D]
    float* att = out + (size_t)B_ * S_ * D_;          // [B,H,S,S]

    cudaFuncSetAttribute(scores_kernel,
                         cudaFuncAttributeMaxDynamicSharedMemorySize, SCORES_SMEM);
    cudaFuncSetAttribute(ctx_kernel,
                         cudaFuncAttributeMaxDynamicSharedMemorySize, CTX_SMEM);

    // 0) transpose weights to [n][k]
    {
        dim3 g1(QKVN / 32, D_ / 32);
        transpose_kernel<<<g1, 256>>>(Wqkv, QKVN, D_, 0);
        dim3 g2(D_ / 32, D_ / 32);
        transpose_kernel<<<g2, 256>>>(Wo, D_, D_, 1);
    }
    // 1) fused QKV projection (ldmatrix-fed tf32 GEMM)
    {
        dim3 grid(QKVN / 128, M_ / 128);
        qkv_gemm_kernel<<<grid, 256>>>(x, bqkv);
    }
    // 2a) e-scores (pre-exponentiated) + half partials
    {
        dim3 grid(S_ / 128, S_ / 128, B_ * H_);
        scores_kernel<<<grid, 256, SCORES_SMEM>>>(mask, att);
    }
    // 2b) ctx = softmax(att) @ V via smem scale table, att normalized in-flight
    {
        dim3 grid(S_ / 128, B_ * H_);
        ctx_kernel<<<grid, 256, CTX_SMEM>>>(att);
    }
    // 3) output projection
    {
        dim3 grid(D_ / 128, M_ / 128);
        out_gemm_kernel<<<grid, 256>>>(bo, out);
    }
}

// round 15
// speedup vs baseline: 1.2018x; 1.0074x over previous
#include <cuda_runtime.h>
#include <cstdint>

// Problem constants
#define B_   4
#define S_   1024
#define D_   1024
#define H_   16
#define HD_  64
#define QKVN 3072
#define M_   (B_ * S_)

// Scratch (static device globals — allocation-free per harness rules)
__device__ float g_qkv[(size_t)M_ * QKVN];     // [b,s, h*192 + {q,k,v}*64]
__device__ float g_ctx[(size_t)M_ * D_];       // [b,s, h*64+d]
__device__ float2 g_part[(size_t)B_ * H_ * S_ * 16];  // per (bh,q,chunk64): (max, expsum)
__device__ float g_wt[(size_t)QKVN * D_];      // Wqkv^T : [n][k]
__device__ float g_wot[(size_t)D_ * D_];       // Wo^T   : [n][k]

// ---------------------------------------------------------------------------
// helpers
// ---------------------------------------------------------------------------
__device__ __forceinline__ float to_tf32(float x) {
    uint32_t u;
    asm("cvt.rna.tf32.f32 %0, %1;" : "=r"(u) : "f"(x));
    return __uint_as_float(u);
}

__device__ __forceinline__ void mma_tf32(float* d, const uint32_t* a, const uint32_t* b) {
    asm volatile(
        "mma.sync.aligned.m16n8k8.row.col.f32.tf32.tf32.f32 "
        "{%0,%1,%2,%3}, {%4,%5,%6,%7}, {%8,%9}, {%0,%1,%2,%3};\n"
        : "+f"(d[0]), "+f"(d[1]), "+f"(d[2]), "+f"(d[3])
        : "r"(a[0]), "r"(a[1]), "r"(a[2]), "r"(a[3]), "r"(b[0]), "r"(b[1]));
}

__device__ __forceinline__ void ldsm_x4(uint32_t& r0, uint32_t& r1,
                                        uint32_t& r2, uint32_t& r3, uint32_t addr) {
    asm volatile("ldmatrix.sync.aligned.m8n8.x4.shared.b16 {%0,%1,%2,%3}, [%4];"
                 : "=r"(r0), "=r"(r1), "=r"(r2), "=r"(r3) : "r"(addr));
}

// ---------------------------------------------------------------------------
// transpose: Wt[n][k] = W[k][n]  (W is [K][N] row-major); dst selected by flag
// ---------------------------------------------------------------------------
__global__ __launch_bounds__(256) void transpose_kernel(
    const float* __restrict__ W, int N, int K, int dst_sel)
{
    float* Wt = dst_sel ? g_wot : g_wt;
    __shared__ float t[32][33];
    const int n0 = blockIdx.x * 32, k0 = blockIdx.y * 32;
    const int tx = threadIdx.x & 31, ty = threadIdx.x >> 5;  // 32 x 8
#pragma unroll
    for (int i = 0; i < 4; i++)
        t[ty + 8 * i][tx] = W[(size_t)(k0 + ty + 8 * i) * N + n0 + tx];
    __syncthreads();
#pragma unroll
    for (int i = 0; i < 4; i++)
        Wt[(size_t)(n0 + ty + 8 * i) * K + k0 + tx] = t[tx][ty + 8 * i];
}

// ---------------------------------------------------------------------------
// tf32 GEMM with ldmatrix fragment feeds (FROZEN from R14).
// ---------------------------------------------------------------------------
#define BK   32
#define TSTR 36

__device__ __forceinline__ void gemm_lds_body(
    const float* __restrict__ A, const float* __restrict__ Bt,
    const float* __restrict__ bias, float* __restrict__ C,
    int N, int K)
{
    __shared__ float As[128 * TSTR];
    __shared__ float Bs[128 * TSTR];

    const int tid  = threadIdx.x;
    const int lane = tid & 31;
    const int wid  = tid >> 5;
    const int wm   = (wid & 3) * 32;
    const int wn   = (wid >> 2) * 64;
    const int bx   = blockIdx.x * 128;
    const int by   = blockIdx.y * 128;

    const int g = lane >> 2;
    const int a = lane & 3;

    float acc[2][8][4];
#pragma unroll
    for (int i = 0; i < 2; i++)
#pragma unroll
        for (int j = 0; j < 8; j++)
#pragma unroll
            for (int v = 0; v < 4; v++) acc[i][j][v] = 0.f;

    const int srow = tid >> 3;
    const int scol = (tid & 7) * 4;

    const uint32_t as_base = (uint32_t)__cvta_generic_to_shared(As);
    const uint32_t bs_base = (uint32_t)__cvta_generic_to_shared(Bs);
    uint32_t aoff[2], boff[4];
#pragma unroll
    for (int i = 0; i < 2; i++)
        aoff[i] = as_base +
            ((wm + i * 16 + ((lane >> 3) & 1) * 8 + (lane & 7)) * TSTR
             + (lane >> 4) * 4) * 4;
#pragma unroll
    for (int jj = 0; jj < 4; jj++)
        boff[jj] = bs_base +
            ((wn + 8 * (2 * jj + (lane >> 4)) + (lane & 7)) * TSTR
             + ((lane >> 3) & 1) * 4) * 4;

    for (int k0 = 0; k0 < K; k0 += BK) {
        float4 av[4], bv[4];
#pragma unroll
        for (int i = 0; i < 4; i++)
            av[i] = *(const float4*)(A + (size_t)(by + srow + 32 * i) * K + k0 + scol);
#pragma unroll
        for (int i = 0; i < 4; i++)
            bv[i] = *(const float4*)(Bt + (size_t)(bx + srow + 32 * i) * K + k0 + scol);

        __syncthreads();
#pragma unroll
        for (int i = 0; i < 4; i++) {
            float4 t = av[i];
            t.x = to_tf32(t.x); t.y = to_tf32(t.y); t.z = to_tf32(t.z); t.w = to_tf32(t.w);
            *(float4*)(As + (srow + 32 * i) * TSTR + scol) = t;
        }
#pragma unroll
        for (int i = 0; i < 4; i++) {
            float4 t = bv[i];
            t.x = to_tf32(t.x); t.y = to_tf32(t.y); t.z = to_tf32(t.z); t.w = to_tf32(t.w);
            *(float4*)(Bs + (srow + 32 * i) * TSTR + scol) = t;
        }
        __syncthreads();

#pragma unroll
        for (int kk = 0; kk < BK; kk += 8) {
            uint32_t af[2][4], bf[8][2];
#pragma unroll
            for (int i = 0; i < 2; i++)
                ldsm_x4(af[i][0], af[i][1], af[i][2], af[i][3], aoff[i] + kk * 4);
#pragma unroll
            for (int jj = 0; jj < 4; jj++)
                ldsm_x4(bf[2 * jj][0], bf[2 * jj][1],
                        bf[2 * jj + 1][0], bf[2 * jj + 1][1], boff[jj] + kk * 4);
#pragma unroll
            for (int i = 0; i < 2; i++)
#pragma unroll
                for (int j = 0; j < 8; j++)
                    mma_tf32(acc[i][j], af[i], bf[j]);
        }
    }

#pragma unroll
    for (int i = 0; i < 2; i++) {
        int row = by + wm + i * 16 + g;
#pragma unroll
        for (int j = 0; j < 8; j++) {
            int col = bx + wn + j * 8 + a * 2;
            float b0 = bias[col], b1 = bias[col + 1];
            *(float2*)(C + (size_t)row * N + col) =
                make_float2(acc[i][j][0] + b0, acc[i][j][1] + b1);
            *(float2*)(C + (size_t)(row + 8) * N + col) =
                make_float2(acc[i][j][2] + b0, acc[i][j][3] + b1);
        }
    }
}

__global__ __launch_bounds__(256) void qkv_gemm_kernel(
    const float* __restrict__ x, const float* __restrict__ bias)
{
    gemm_lds_body(x, g_wt, bias, g_qkv, QKVN, D_);
}

__global__ __launch_bounds__(256) void out_gemm_kernel(
    const float* __restrict__ bias, float* __restrict__ out)
{
    gemm_lds_body(g_ctx, g_wot, bias, out, D_, D_);
}

// ---------------------------------------------------------------------------
// scores kernel: now ldmatrix-fed (Q/K tiles [row][k] stride 68, CF for LDSM).
// s = (Q*0.125)K^T + mask; writes e = exp(s - m_half) + half partials.
// ---------------------------------------------------------------------------
#define SC_STR 68
#define SCORES_SMEM ((128 * SC_STR * 2) * 4)

__global__ __launch_bounds__(256) void scores_kernel(
    const float* __restrict__ mask, float* __restrict__ att)
{
    extern __shared__ float sms[];
    float* Qs = sms;
    float* Ks = sms + 128 * SC_STR;

    const int bh = blockIdx.z;
    const int b  = bh >> 4, h = bh & 15;
    const int qt = blockIdx.y * 128;
    const int kt = blockIdx.x * 128;
    const int tid = threadIdx.x;
    const int lane = tid & 31, w = tid >> 5;
    const int g = lane >> 2, a = lane & 3;
    const int wm = (w & 3) * 32, wn = (w >> 2) * 64;

    const float* qkv_b = g_qkv + (size_t)(b * S_) * QKVN + h * 192;

    {
        int row = tid >> 4;
        int c4  = (tid & 15) * 4;
#pragma unroll
        for (int i = 0; i < 8; i++) {
            float4 t = *(const float4*)(qkv_b + (size_t)(qt + row + 16 * i) * QKVN + c4);
            t.x = to_tf32(t.x * 0.125f); t.y = to_tf32(t.y * 0.125f);
            t.z = to_tf32(t.z * 0.125f); t.w = to_tf32(t.w * 0.125f);
            *(float4*)(Qs + (row + 16 * i) * SC_STR + c4) = t;
        }
#pragma unroll
        for (int i = 0; i < 8; i++) {
            float4 t = *(const float4*)(qkv_b + (size_t)(kt + row + 16 * i) * QKVN + 64 + c4);
            t.x = to_tf32(t.x); t.y = to_tf32(t.y); t.z = to_tf32(t.z); t.w = to_tf32(t.w);
            *(float4*)(Ks + (row + 16 * i) * SC_STR + c4) = t;
        }
    }
    __syncthreads();

    // ldmatrix lane offsets
    const uint32_t qs_base = (uint32_t)__cvta_generic_to_shared(Qs);
    const uint32_t ks_base = (uint32_t)__cvta_generic_to_shared(Ks);
    uint32_t aoff[2], boff[4];
#pragma unroll
    for (int i = 0; i < 2; i++)
        aoff[i] = qs_base +
            ((wm + i * 16 + ((lane >> 3) & 1) * 8 + (lane & 7)) * SC_STR
             + (lane >> 4) * 4) * 4;
#pragma unroll
    for (int jj = 0; jj < 4; jj++)
        boff[jj] = ks_base +
            ((wn + 8 * (2 * jj + (lane >> 4)) + (lane & 7)) * SC_STR
             + ((lane >> 3) & 1) * 4) * 4;

    float acc[2][8][4];
#pragma unroll
    for (int i = 0; i < 2; i++)
#pragma unroll
        for (int j = 0; j < 8; j++)
#pragma unroll
            for (int v = 0; v < 4; v++) acc[i][j][v] = 0.f;

#pragma unroll
    for (int ks = 0; ks < 8; ks++) {
        int k0 = ks * 8;
        uint32_t af[2][4], bf[8][2];
#pragma unroll
        for (int i = 0; i < 2; i++)
            ldsm_x4(af[i][0], af[i][1], af[i][2], af[i][3], aoff[i] + k0 * 4);
#pragma unroll
        for (int jj = 0; jj < 4; jj++)
            ldsm_x4(bf[2 * jj][0], bf[2 * jj][1],
                    bf[2 * jj + 1][0], bf[2 * jj + 1][1], boff[jj] + k0 * 4);
#pragma unroll
        for (int i = 0; i < 2; i++)
#pragma unroll
            for (int j = 0; j < 8; j++)
                mma_tf32(acc[i][j], af[i], bf[j]);
    }

    float* abase = att + ((size_t)(b * H_ + h) * S_ + qt) * S_ + kt;
    const float* mbase = mask + ((size_t)(b * S_) + qt) * S_ + kt;
    const int half = wn >> 6;
#pragma unroll
    for (int i = 0; i < 2; i++) {
        int r0 = wm + i * 16 + g;
        float mx0 = -1e30f, mx1 = -1e30f;
#pragma unroll
        for (int j = 0; j < 8; j++) {
            int col = wn + j * 8 + a * 2;
            float2 m0 = *(const float2*)(mbase + (size_t)r0 * S_ + col);
            float2 m1 = *(const float2*)(mbase + (size_t)(r0 + 8) * S_ + col);
            acc[i][j][0] += m0.x; acc[i][j][1] += m0.y;
            acc[i][j][2] += m1.x; acc[i][j][3] += m1.y;
            mx0 = fmaxf(mx0, fmaxf(acc[i][j][0], acc[i][j][1]));
            mx1 = fmaxf(mx1, fmaxf(acc[i][j][2], acc[i][j][3]));
        }
        mx0 = fmaxf(mx0, __shfl_xor_sync(~0u, mx0, 1));
        mx0 = fmaxf(mx0, __shfl_xor_sync(~0u, mx0, 2));
        mx1 = fmaxf(mx1, __shfl_xor_sync(~0u, mx1, 1));
        mx1 = fmaxf(mx1, __shfl_xor_sync(~0u, mx1, 2));
        float s0 = 0.f, s1 = 0.f;
#pragma unroll
        for (int j = 0; j < 8; j++) {
            int col = wn + j * 8 + a * 2;
            float e00 = __expf(acc[i][j][0] - mx0);
            float e01 = __expf(acc[i][j][1] - mx0);
            float e10 = __expf(acc[i][j][2] - mx1);
            float e11 = __expf(acc[i][j][3] - mx1);
            s0 += e00 + e01;
            s1 += e10 + e11;
            *(float2*)(abase + (size_t)r0 * S_ + col)       = make_float2(e00, e01);
            *(float2*)(abase + (size_t)(r0 + 8) * S_ + col) = make_float2(e10, e11);
        }
        s0 += __shfl_xor_sync(~0u, s0, 1); s0 += __shfl_xor_sync(~0u, s0, 2);
        s1 += __shfl_xor_sync(~0u, s1, 1); s1 += __shfl_xor_sync(~0u, s1, 2);
        if (a == 0) {
            g_part[((size_t)bh * S_ + qt + r0)     * 16 + blockIdx.x * 2 + half] =
                make_float2(mx0, s0);
            g_part[((size_t)bh * S_ + qt + r0 + 8) * 16 + blockIdx.x * 2 + half] =
                make_float2(mx1, s1);
        }
    }
}

// ---------------------------------------------------------------------------
// ctx kernel: A-frags via ldmatrix (stride 68 CF); V frags scalar (k-major).
// smem scale table + P@V, att normalized in-flight.
// ---------------------------------------------------------------------------
#define CT_ASTR 68
#define CT_VSTR 72
#define CT_AT   (128 * CT_ASTR)
#define CT_VT   (64 * CT_VSTR)
#define CTX_SMEM (2 * (CT_AT + CT_VT) * 4)

__global__ __launch_bounds__(256) void ctx_kernel(float* __restrict__ att)
{
    extern __shared__ float smcx[];
    float* As = smcx;
    float* Vs = smcx + 2 * CT_AT;
    __shared__ float sm_scale[16][128];   // [chunk64][row]

    const int bh = blockIdx.y;
    const int b  = bh >> 4, h = bh & 15;
    const int mt = blockIdx.x * 128;
    const int tid = threadIdx.x;
    const int lane = tid & 31, w = tid >> 5;
    const int g = lane >> 2, a = lane & 3;
    const int wm = (w & 3) * 32, wn = (w >> 2) * 32;

    float* abase = att + ((size_t)bh * S_ + mt) * S_;
    const float* vbase = g_qkv + (size_t)(b * S_) * QKVN + h * 192 + 128;

    const int lrow = tid >> 4;
    const int lc4  = (tid & 15) * 4;

    if (tid < 128) {
        const float2* pp = g_part + ((size_t)bh * S_ + mt + tid) * 16;
        float2 t[16];
#pragma unroll
        for (int k = 0; k < 16; k++) t[k] = pp[k];
        float M = t[0].x;
#pragma unroll
        for (int k = 1; k < 16; k++) M = fmaxf(M, t[k].x);
        float es[16];
        float S = 0.f;
#pragma unroll
        for (int k = 0; k < 16; k++) {
            es[k] = __expf(t[k].x - M);
            S += t[k].y * es[k];
        }
        float inv = 1.f / S;
#pragma unroll
        for (int k = 0; k < 16; k++) sm_scale[k][tid] = es[k] * inv;
    }
    __syncthreads();

    // ldmatrix A lane offsets (relative; add buffer offset per chunk)
    const uint32_t as_base = (uint32_t)__cvta_generic_to_shared(As);
    uint32_t arel[2];
#pragma unroll
    for (int i = 0; i < 2; i++)
        arel[i] = ((wm + i * 16 + ((lane >> 3) & 1) * 8 + (lane & 7)) * CT_ASTR
                   + (lane >> 4) * 4) * 4;

    float4 avr[8], bvr[4];

#define A_LDG(c)                                                               \
    {                                                                          \
        _Pragma("unroll")                                                      \
        for (int i = 0; i < 8; i++)                                            \
            avr[i] = *(const float4*)(abase + (size_t)(lrow + 16 * i) * S_ +   \
                                      (c) * 64 + lc4);                         \
    }
#define A_STS(buf, c)                                                          \
    {                                                                          \
        float* dst = As + (buf) * CT_AT;                                       \
        _Pragma("unroll")                                                      \
        for (int i = 0; i < 8; i++) {                                          \
            float sc_i = sm_scale[c][lrow + 16 * i];                           \
            float4 t = avr[i];                                                 \
            t.x *= sc_i; t.y *= sc_i; t.z *= sc_i; t.w *= sc_i;                \
            *(float4*)(abase + (size_t)(lrow + 16 * i) * S_ + (c) * 64 + lc4) = t; \
            t.x = to_tf32(t.x); t.y = to_tf32(t.y);                            \
            t.z = to_tf32(t.z); t.w = to_tf32(t.w);                            \
            *(float4*)(dst + (lrow + 16 * i) * CT_ASTR + lc4) = t;             \
        }                                                                      \
    }
#define V_LDG(c)                                                               \
    {                                                                          \
        _Pragma("unroll")                                                      \
        for (int i = 0; i < 4; i++)                                            \
            bvr[i] = *(const float4*)(vbase +                                  \
                (size_t)((c) * 64 + lrow + 16 * i) * QKVN + lc4);              \
    }
#define V_STS(buf)                                                             \
    {                                                                          \
        float* dst = Vs + (buf) * CT_VT;                                       \
        _Pragma("unroll")                                                      \
        for (int i = 0; i < 4; i++) {                                          \
            float4 t = bvr[i];                                                 \
            t.x = to_tf32(t.x); t.y = to_tf32(t.y);                            \
            t.z = to_tf32(t.z); t.w = to_tf32(t.w);                            \
            *(float4*)(dst + (lrow + 16 * i) * CT_VSTR + lc4) = t;             \
        }                                                                      \
    }

    float acc[2][4][4];
#pragma unroll
    for (int i = 0; i < 2; i++)
#pragma unroll
        for (int j = 0; j < 4; j++)
#pragma unroll
            for (int v = 0; v < 4; v++) acc[i][j][v] = 0.f;

    const int nk = S_ / 64;
    A_LDG(0); A_STS(0, 0);
    V_LDG(0); V_STS(0);
    A_LDG(1); V_LDG(1);
    __syncthreads();

    for (int c = 0; c < nk; c++) {
        const float* Vb_ = Vs + (c & 1) * CT_VT;
        const uint32_t abuf = as_base + (uint32_t)((c & 1) * CT_AT * 4);
        if (c + 1 < nk) { A_STS((c + 1) & 1, c + 1); V_STS((c + 1) & 1); }
        if (c + 2 < nk) { A_LDG(c + 2); V_LDG(c + 2); }

#pragma unroll
        for (int kk = 0; kk < 64; kk += 8) {
            uint32_t af[2][4], bf[4][2];
#pragma unroll
            for (int i = 0; i < 2; i++)
                ldsm_x4(af[i][0], af[i][1], af[i][2], af[i][3],
                        abuf + arel[i] + kk * 4);
#pragma unroll
            for (int j = 0; j < 4; j++) {
                int n = wn + j * 8 + g;
                bf[j][0] = __float_as_uint(Vb_[(kk + a)     * CT_VSTR + n]);
                bf[j][1] = __float_as_uint(Vb_[(kk + 4 + a) * CT_VSTR + n]);
            }
#pragma unroll
            for (int i = 0; i < 2; i++)
#pragma unroll
                for (int j = 0; j < 4; j++)
                    mma_tf32(acc[i][j], af[i], bf[j]);
        }
        __syncthreads();
    }
#undef A_LDG
#undef A_STS
#undef V_LDG
#undef V_STS

#pragma unroll
    for (int i = 0; i < 2; i++) {
        int row = mt + wm + i * 16 + g;
#pragma unroll
        for (int j = 0; j < 4; j++) {
            int col = wn + j * 8 + a * 2;
            *(float2*)(g_ctx + (size_t)(b * S_ + row) * D_ + h * HD_ + col) =
                make_float2(acc[i][j][0], acc[i][j][1]);
            *(float2*)(g_ctx + (size_t)(b * S_ + row + 8) * D_ + h * HD_ + col) =
                make_float2(acc[i][j][2], acc[i][j][3]);
        }
    }
}

// ---------------------------------------------------------------------------
extern "C" void kernel_launch(void* const* d_in, const int* in_sizes, int n_in,
                              void* d_out, int out_size)
{
    const float* x    = (const float*)d_in[0];
    const float* mask = (const float*)d_in[1];
    const float* Wqkv = (const float*)d_in[2];
    const float* bqkv = (const float*)d_in[3];
    const float* Wo   = (const float*)d_in[4];
    const float* bo   = (const float*)d_in[5];

    float* out = (float*)d_out;                       // [B,S,D]
    float* att = out + (size_t)B_ * S_ * D_;          // [B,H,S,S]

    cudaFuncSetAttribute(scores_kernel,
                         cudaFuncAttributeMaxDynamicSharedMemorySize, SCORES_SMEM);
    cudaFuncSetAttribute(ctx_kernel,
                         cudaFuncAttributeMaxDynamicSharedMemorySize, CTX_SMEM);

    // 0) transpose weights to [n][k]
    {
        dim3 g1(QKVN / 32, D_ / 32);
        transpose_kernel<<<g1, 256>>>(Wqkv, QKVN, D_, 0);
        dim3 g2(D_ / 32, D_ / 32);
        transpose_kernel<<<g2, 256>>>(Wo, D_, D_, 1);
    }
    // 1) fused QKV projection (ldmatrix-fed tf32 GEMM)
    {
        dim3 grid(QKVN / 128, M_ / 128);
        qkv_gemm_kernel<<<grid, 256>>>(x, bqkv);
    }
    // 2a) e-scores (pre-exponentiated) + half partials, ldmatrix-fed
    {
        dim3 grid(S_ / 128, S_ / 128, B_ * H_);
        scores_kernel<<<grid, 256, SCORES_SMEM>>>(mask, att);
    }
    // 2b) ctx = softmax(att) @ V, A-frags via ldmatrix
    {
        dim3 grid(S_ / 128, B_ * H_);
        ctx_kernel<<<grid, 256, CTX_SMEM>>>(att);
    }
    // 3) output projection
    {
        dim3 grid(D_ / 128, M_ / 128);
        out_gemm_kernel<<<grid, 256>>>(bo, out);
    }
}